// round 7
// baseline (speedup 1.0000x reference)
#include <cuda_runtime.h>
#include <cuda_bf16.h>
#include <cstdint>

#define NN 50000
#define NE 800000
#define ET 850000   // NE + NN self loops
#define NG 100
#define C1 256      // heads*hid = 4*64
#define H1 4
#define CH1 64
#define C2 128
#define NEG_SLOPE 0.2f
#define EPSV 1e-16f

// ---------------- scratch (device globals; no allocation allowed) ----------------
__device__ __align__(16) float g_h1[NN * C1];     // x @ W1
__device__ __align__(16) float g_out1[NN * C1];   // layer-1 aggregated (then finalized in place)
__device__ __align__(16) float g_h2[NN * C2];     // relu(out1) @ W2
__device__ __align__(16) float g_out2[NN * C2];   // layer-2 aggregated
__device__ __align__(16) float g_asrc1[NN * H1];
__device__ __align__(16) float g_adst1[NN * H1];
__device__ float g_denom1[NN * H1];
__device__ float g_asrc2[NN], g_adst2[NN];
__device__ float g_denom2[NN];
__device__ float g_cnt[NG];

// ---------------- helpers ----------------
__device__ __forceinline__ float lrelu(float a) { return a > 0.f ? a : NEG_SLOPE * a; }

// ---------------- init: zero all accumulators ----------------
__global__ void init_kernel(float* __restrict__ pool) {
    int i = blockIdx.x * blockDim.x + threadIdx.x;
    if (i < NN * C1) g_out1[i] = 0.f;
    if (i < NN * C2) g_out2[i] = 0.f;
    if (i < NN * H1) g_denom1[i] = 0.f;
    if (i < NN)      g_denom2[i] = 0.f;
    if (i < NG * C2) pool[i] = 0.f;
    if (i < NG)      g_cnt[i] = 0.f;
}

// ---------------- SGEMM: C[M,N] = A[M,K] @ B[K,N], row-major fp32 ----------------
// BM=128 BN=128 BK=16, 256 threads, 8x8 micro-tile, double-buffered smem.
// Requires: N % 128 == 0, K % 16 == 0. M guarded.
__global__ __launch_bounds__(256) void sgemm128_kernel(
    const float* __restrict__ A, const float* __restrict__ B, float* __restrict__ C,
    int M, int N, int K)
{
    __shared__ float As[2][16][128];   // As[buf][k][m]
    __shared__ float Bs[2][16][128];   // Bs[buf][k][n]

    const int bm = blockIdx.y * 128;
    const int bn = blockIdx.x * 128;
    const int t  = threadIdx.x;

    // A tile loaders: 128 rows x 16 cols; thread covers rows (t>>2) and (t>>2)+64, cols (t&3)*4
    const int ar = t >> 2;            // 0..63
    const int ac = (t & 3) * 4;       // 0,4,8,12
    // B tile loaders: 16 rows x 128 cols; thread covers rows (t>>5) and (t>>5)+8, cols (t&31)*4
    const int br = t >> 5;            // 0..7
    const int bc = (t & 31) * 4;      // 0..124

    const int tx = t & 15;            // 16 col groups of 8
    const int ty = t >> 4;            // 16 row groups of 8

    float acc[8][8] = {};
    float4 pa0, pa1, pb0, pb1;

    const int NT = K / 16;

    // load tile 0 into buffer 0
    {
        pa0 = make_float4(0.f, 0.f, 0.f, 0.f); pa1 = pa0;
        if (bm + ar < M)      pa0 = *(const float4*)(A + (size_t)(bm + ar) * K + ac);
        if (bm + ar + 64 < M) pa1 = *(const float4*)(A + (size_t)(bm + ar + 64) * K + ac);
        pb0 = *(const float4*)(B + (size_t)br * N + bn + bc);
        pb1 = *(const float4*)(B + (size_t)(br + 8) * N + bn + bc);
        As[0][ac + 0][ar] = pa0.x; As[0][ac + 1][ar] = pa0.y;
        As[0][ac + 2][ar] = pa0.z; As[0][ac + 3][ar] = pa0.w;
        As[0][ac + 0][ar + 64] = pa1.x; As[0][ac + 1][ar + 64] = pa1.y;
        As[0][ac + 2][ar + 64] = pa1.z; As[0][ac + 3][ar + 64] = pa1.w;
        *(float4*)&Bs[0][br][bc]     = pb0;
        *(float4*)&Bs[0][br + 8][bc] = pb1;
    }
    __syncthreads();

    int buf = 0;
    for (int it = 0; it < NT; it++) {
        // prefetch next tile into registers
        if (it + 1 < NT) {
            int k0 = (it + 1) * 16;
            pa0 = make_float4(0.f, 0.f, 0.f, 0.f); pa1 = pa0;
            if (bm + ar < M)      pa0 = *(const float4*)(A + (size_t)(bm + ar) * K + k0 + ac);
            if (bm + ar + 64 < M) pa1 = *(const float4*)(A + (size_t)(bm + ar + 64) * K + k0 + ac);
            pb0 = *(const float4*)(B + (size_t)(k0 + br) * N + bn + bc);
            pb1 = *(const float4*)(B + (size_t)(k0 + br + 8) * N + bn + bc);
        }
        // compute on current buffer
#pragma unroll
        for (int k = 0; k < 16; k++) {
            float4 x0 = *(const float4*)&As[buf][k][ty * 8];
            float4 x1 = *(const float4*)&As[buf][k][ty * 8 + 4];
            float4 y0 = *(const float4*)&Bs[buf][k][tx * 8];
            float4 y1 = *(const float4*)&Bs[buf][k][tx * 8 + 4];
            float a[8] = {x0.x, x0.y, x0.z, x0.w, x1.x, x1.y, x1.z, x1.w};
            float b[8] = {y0.x, y0.y, y0.z, y0.w, y1.x, y1.y, y1.z, y1.w};
#pragma unroll
            for (int i = 0; i < 8; i++)
#pragma unroll
                for (int j = 0; j < 8; j++)
                    acc[i][j] += a[i] * b[j];
        }
        // store prefetched tile into other buffer
        if (it + 1 < NT) {
            int nb = buf ^ 1;
            As[nb][ac + 0][ar] = pa0.x; As[nb][ac + 1][ar] = pa0.y;
            As[nb][ac + 2][ar] = pa0.z; As[nb][ac + 3][ar] = pa0.w;
            As[nb][ac + 0][ar + 64] = pa1.x; As[nb][ac + 1][ar + 64] = pa1.y;
            As[nb][ac + 2][ar + 64] = pa1.z; As[nb][ac + 3][ar + 64] = pa1.w;
            *(float4*)&Bs[nb][br][bc]     = pb0;
            *(float4*)&Bs[nb][br + 8][bc] = pb1;
        }
        __syncthreads();
        buf ^= 1;
    }

#pragma unroll
    for (int i = 0; i < 8; i++) {
        int row = bm + ty * 8 + i;
        if (row < M) {
            *(float4*)(C + (size_t)row * N + bn + tx * 8)     = make_float4(acc[i][0], acc[i][1], acc[i][2], acc[i][3]);
            *(float4*)(C + (size_t)row * N + bn + tx * 8 + 4) = make_float4(acc[i][4], acc[i][5], acc[i][6], acc[i][7]);
        }
    }
}

// ---------------- attention scores: a_src[n,h] = <h[n,h,:], att_src[h,:]> ----------------
__global__ void attn_scores_kernel(const float* __restrict__ h,
                                   const float* __restrict__ att_s,
                                   const float* __restrict__ att_d,
                                   float* __restrict__ asrc, float* __restrict__ adst,
                                   int heads, int ch)
{
    int i = blockIdx.x * blockDim.x + threadIdx.x;
    if (i >= NN * heads) return;
    int node = i / heads, hd = i - node * heads;
    const float4* hp = (const float4*)(h + (size_t)node * heads * ch + hd * ch);
    const float4* sp = (const float4*)(att_s + hd * ch);
    const float4* dp = (const float4*)(att_d + hd * ch);
    float s = 0.f, d = 0.f;
    for (int c = 0; c < ch / 4; c++) {
        float4 v = hp[c], a = sp[c], b = dp[c];
        s += v.x * a.x + v.y * a.y + v.z * a.z + v.w * a.w;
        d += v.x * b.x + v.y * b.y + v.z * b.z + v.w * b.w;
    }
    asrc[i] = s; adst[i] = d;
}

// ---------------- edge pass: e=exp(lrelu(alpha)); denom += e; out[dst] += h[src]*e ----------------
// No segment-max: softmax is shift-invariant and |alpha| is O(1) here (no overflow possible).
// One warp per edge. C channels split over 32 lanes (CPL = C/32 each, float4 chunks).
template <int H, int C>
__global__ __launch_bounds__(256) void edge_accum_kernel(
    const int* __restrict__ ei,
    const float* __restrict__ h,
    const float* __restrict__ asrc, const float* __restrict__ adst,
    float* __restrict__ denom, float* __restrict__ out)
{
    int warp = (blockIdx.x * blockDim.x + threadIdx.x) >> 5;
    int lane = threadIdx.x & 31;
    if (warp >= ET) return;
    int s, dn;
    if (warp < NE) { s = ei[warp]; dn = ei[NE + warp]; }
    else           { s = dn = warp - NE; }

    constexpr int CPL = C / 32;          // channels per lane
    constexpr int CH  = C / H;           // channels per head
    const int hd = (lane * CPL) / CH;    // head owning this lane's channels

    float a = lrelu(asrc[s * H + hd] + adst[dn * H + hd]);
    float e = __expf(a);

    if ((lane % (32 / H)) == 0) atomicAdd(&denom[dn * H + hd], e);

    const float4* hp = (const float4*)(h + (size_t)s * C);
    float* op = out + (size_t)dn * C + lane * CPL;
#pragma unroll
    for (int j = 0; j < CPL / 4; j++) {
        float4 v = hp[lane * (CPL / 4) + j];
        v.x *= e; v.y *= e; v.z *= e; v.w *= e;
        asm volatile("red.global.add.v4.f32 [%0], {%1,%2,%3,%4};"
                     :: "l"(op + j * 4), "f"(v.x), "f"(v.y), "f"(v.z), "f"(v.w)
                     : "memory");
    }
}

// ---------------- layer-1 finalize: out = relu(out/(denom+eps) + bias) ----------------
__global__ void finalize1_kernel(const float* __restrict__ bias) {
    int i = blockIdx.x * blockDim.x + threadIdx.x;
    if (i >= NN * C1) return;
    int n = i >> 8, c = i & 255, hd = c >> 6;
    float v = g_out1[i] / (g_denom1[n * H1 + hd] + EPSV) + bias[c];
    g_out1[i] = v > 0.f ? v : 0.f;
}

// ---------------- layer-2 finalize + pooled sum ----------------
__global__ void finalize2_pool_kernel(const float* __restrict__ bias,
                                      const int* __restrict__ batch,
                                      float* __restrict__ pool) {
    int i = blockIdx.x * blockDim.x + threadIdx.x;
    if (i >= NN * C2) return;
    int n = i >> 7, c = i & 127;
    float v = g_out2[i] / (g_denom2[n] + EPSV) + bias[c];
    v = v > 0.f ? v : 0.f;
    int g = batch[n];
    atomicAdd(&pool[g * C2 + c], v);
    if (c == 0) atomicAdd(&g_cnt[g], 1.0f);
}

__global__ void pool_div_kernel(float* __restrict__ pool) {
    int i = blockIdx.x * blockDim.x + threadIdx.x;
    if (i >= NG * C2) return;
    int g = i >> 7;
    float c = g_cnt[g];
    pool[i] = pool[i] / (c > 1.f ? c : 1.f);
}

// ---------------- host launcher (graph-capturable, default stream) ----------------
extern "C" void kernel_launch(void* const* d_in, const int* in_sizes, int n_in,
                              void* d_out, int out_size)
{
    const float* x    = (const float*)d_in[0];
    const float* W1   = (const float*)d_in[1];
    const float* as1  = (const float*)d_in[2];
    const float* ad1  = (const float*)d_in[3];
    const float* b1   = (const float*)d_in[4];
    const float* W2   = (const float*)d_in[5];
    const float* as2  = (const float*)d_in[6];
    const float* ad2  = (const float*)d_in[7];
    const float* b2   = (const float*)d_in[8];
    const int*   ei   = (const int*)d_in[9];     // int32
    const int*   batch= (const int*)d_in[10];    // int32
    float* pool = (float*)d_out;

    float *p_h1, *p_out1, *p_h2, *p_out2;
    float *p_asrc1, *p_adst1, *p_denom1, *p_asrc2, *p_adst2, *p_denom2;
    cudaGetSymbolAddress((void**)&p_h1, g_h1);
    cudaGetSymbolAddress((void**)&p_out1, g_out1);
    cudaGetSymbolAddress((void**)&p_h2, g_h2);
    cudaGetSymbolAddress((void**)&p_out2, g_out2);
    cudaGetSymbolAddress((void**)&p_asrc1, g_asrc1);
    cudaGetSymbolAddress((void**)&p_adst1, g_adst1);
    cudaGetSymbolAddress((void**)&p_denom1, g_denom1);
    cudaGetSymbolAddress((void**)&p_asrc2, g_asrc2);
    cudaGetSymbolAddress((void**)&p_adst2, g_adst2);
    cudaGetSymbolAddress((void**)&p_denom2, g_denom2);

    const int TB = 256;

    // 0) init accumulators + output
    init_kernel<<<(NN * C1 + TB - 1) / TB, TB>>>(pool);

    // 1) h1 = x @ W1   (50000x256x256)
    {
        dim3 grid(C1 / 128, (NN + 127) / 128);
        sgemm128_kernel<<<grid, 256>>>(x, W1, p_h1, NN, C1, 256);
    }
    // 2) attention scores layer 1
    attn_scores_kernel<<<(NN * H1 + TB - 1) / TB, TB>>>(p_h1, as1, ad1, p_asrc1, p_adst1, H1, CH1);
    // 3) exp + denom + message accumulate (warp per edge; no max pass needed)
    {
        long long threads = (long long)ET * 32;
        edge_accum_kernel<H1, C1><<<(unsigned)((threads + TB - 1) / TB), TB>>>(
            ei, p_h1, p_asrc1, p_adst1, p_denom1, p_out1);
    }
    // 4) finalize layer 1 (normalize + bias + relu) in place
    finalize1_kernel<<<(NN * C1 + TB - 1) / TB, TB>>>(b1);

    // 5) h2 = relu_out1 @ W2   (50000x256x128)
    {
        dim3 grid(C2 / 128, (NN + 127) / 128);
        sgemm128_kernel<<<grid, 256>>>(p_out1, W2, p_h2, NN, C2, 256);
    }
    // 6) attention scores layer 2 (1 head, 128 ch)
    attn_scores_kernel<<<(NN + TB - 1) / TB, TB>>>(p_h2, as2, ad2, p_asrc2, p_adst2, 1, C2);
    // 7) accumulate layer 2
    {
        long long threads = (long long)ET * 32;
        edge_accum_kernel<1, C2><<<(unsigned)((threads + TB - 1) / TB), TB>>>(
            ei, p_h2, p_asrc2, p_adst2, p_denom2, p_out2);
    }
    // 8) finalize layer 2 + pooled sums
    finalize2_pool_kernel<<<(NN * C2 + TB - 1) / TB, TB>>>(b2, batch, pool);
    // 9) mean
    pool_div_kernel<<<(NG * C2 + TB - 1) / TB, TB>>>(pool);
}

// round 9
// speedup vs baseline: 1.9866x; 1.9866x over previous
#include <cuda_runtime.h>
#include <cuda_bf16.h>
#include <cstdint>

#define NN 50000
#define NE 800000
#define ET 850000   // NE + NN self loops
#define NG 100
#define C1 256      // heads*hid = 4*64
#define H1 4
#define CH1 64
#define C2 128
#define NEG_SLOPE 0.2f
#define EPSV 1e-16f

// ---------------- scratch (device globals; no allocation allowed) ----------------
__device__ __align__(16) float g_h1[NN * C1];      // x @ W1 (fp32)
__device__ __align__(16) float g_out1[NN * C1];    // layer-1 final (fp32, GEMM2 input)
__device__ __align__(16) float g_h2[NN * C2];      // relu_out1 @ W2 (fp32)
__device__ __align__(16) __nv_bfloat16 g_hb1[NN * C1];  // bf16 copy of h1 for gather
__device__ __align__(16) __nv_bfloat16 g_hb2[NN * C2];  // bf16 copy of h2 for gather
__device__ __align__(16) float g_asrc1[NN * H1];
__device__ __align__(16) float g_adst1[NN * H1];
__device__ float g_asrc2[NN], g_adst2[NN];
__device__ float g_cnt[NG];
// CSR scratch
__device__ int g_hist[NN];
__device__ int g_indptr[NN + 1];
__device__ int g_off[NN];
__device__ int g_esrc[ET];

__device__ __forceinline__ float lrelu(float a) { return a > 0.f ? a : NEG_SLOPE * a; }

// ---------------- init: zero histogram + pool + cnt ----------------
__global__ void init_kernel(float* __restrict__ pool) {
    int i = blockIdx.x * blockDim.x + threadIdx.x;
    if (i < NN)      g_hist[i] = 0;
    if (i < NG * C2) pool[i] = 0.f;
    if (i < NG)      g_cnt[i] = 0.f;
}

// ---------------- CSR build: histogram of dst ----------------
__global__ void hist_kernel(const int* __restrict__ ei) {
    int e = blockIdx.x * blockDim.x + threadIdx.x;
    if (e >= ET) return;
    int dn = (e < NE) ? ei[NE + e] : (e - NE);
    atomicAdd(&g_hist[dn], 1);
}

// ---------------- CSR build: exclusive scan (single block, sequential chunks) ----------------
__global__ void scan_kernel() {
    __shared__ int temp[1024];
    __shared__ int carry;
    const int t = threadIdx.x;
    if (t == 0) carry = 0;
    __syncthreads();
    for (int chunk = 0; chunk < NN; chunk += 1024) {
        int v = (chunk + t < NN) ? g_hist[chunk + t] : 0;
        temp[t] = v;
        __syncthreads();
        // inclusive scan (Hillis-Steele)
        for (int d = 1; d < 1024; d <<= 1) {
            int x = (t >= d) ? temp[t - d] : 0;
            __syncthreads();
            temp[t] += x;
            __syncthreads();
        }
        int excl = temp[t] - v;
        if (chunk + t < NN) {
            g_indptr[chunk + t] = carry + excl;
            g_off[chunk + t]    = carry + excl;
        }
        __syncthreads();
        if (t == 1023) carry += temp[1023];
        __syncthreads();
    }
    if (t == 0) g_indptr[NN] = carry;
}

// ---------------- CSR build: scatter src ids grouped by dst ----------------
__global__ void scatter_kernel(const int* __restrict__ ei) {
    int e = blockIdx.x * blockDim.x + threadIdx.x;
    if (e >= ET) return;
    int s, dn;
    if (e < NE) { s = ei[e]; dn = ei[NE + e]; }
    else        { s = dn = e - NE; }
    int pos = atomicAdd(&g_off[dn], 1);
    g_esrc[pos] = s;
}

// ---------------- SGEMM: C[M,N] = A[M,K] @ B[K,N], row-major fp32 (round-6 version) ----------------
__global__ __launch_bounds__(256) void sgemm_kernel(
    const float* __restrict__ A, const float* __restrict__ B, float* __restrict__ C,
    int M, int N, int K)
{
    __shared__ float As[16][64];
    __shared__ float Bs[16][64];
    const int bm = blockIdx.y * 64;
    const int bn = blockIdx.x * 64;
    const int t = threadIdx.x;
    const int tx = t & 15, ty = t >> 4;
    const int arow = t >> 2, ac = (t & 3) * 4;
    const int brow = t >> 4, bc = (t & 15) * 4;

    float acc[4][4] = {};
    for (int k0 = 0; k0 < K; k0 += 16) {
        float4 av = make_float4(0.f, 0.f, 0.f, 0.f);
        if (bm + arow < M)
            av = *(const float4*)(A + (size_t)(bm + arow) * K + k0 + ac);
        As[ac + 0][arow] = av.x; As[ac + 1][arow] = av.y;
        As[ac + 2][arow] = av.z; As[ac + 3][arow] = av.w;
        *(float4*)&Bs[brow][bc] = *(const float4*)(B + (size_t)(k0 + brow) * N + bn + bc);
        __syncthreads();
#pragma unroll
        for (int k = 0; k < 16; k++) {
            float a0 = As[k][ty * 4 + 0], a1 = As[k][ty * 4 + 1];
            float a2 = As[k][ty * 4 + 2], a3 = As[k][ty * 4 + 3];
            float b0 = Bs[k][tx * 4 + 0], b1 = Bs[k][tx * 4 + 1];
            float b2 = Bs[k][tx * 4 + 2], b3 = Bs[k][tx * 4 + 3];
            acc[0][0] += a0 * b0; acc[0][1] += a0 * b1; acc[0][2] += a0 * b2; acc[0][3] += a0 * b3;
            acc[1][0] += a1 * b0; acc[1][1] += a1 * b1; acc[1][2] += a1 * b2; acc[1][3] += a1 * b3;
            acc[2][0] += a2 * b0; acc[2][1] += a2 * b1; acc[2][2] += a2 * b2; acc[2][3] += a2 * b3;
            acc[3][0] += a3 * b0; acc[3][1] += a3 * b1; acc[3][2] += a3 * b2; acc[3][3] += a3 * b3;
        }
        __syncthreads();
    }
#pragma unroll
    for (int i = 0; i < 4; i++) {
        int row = bm + ty * 4 + i;
        if (row < M) {
            float4 v = make_float4(acc[i][0], acc[i][1], acc[i][2], acc[i][3]);
            *(float4*)(C + (size_t)row * N + bn + tx * 4) = v;
        }
    }
}

// ---------------- attention scores ----------------
__global__ void attn_scores_kernel(const float* __restrict__ h,
                                   const float* __restrict__ att_s,
                                   const float* __restrict__ att_d,
                                   float* __restrict__ asrc, float* __restrict__ adst,
                                   int heads, int ch)
{
    int i = blockIdx.x * blockDim.x + threadIdx.x;
    if (i >= NN * heads) return;
    int node = i / heads, hd = i - node * heads;
    const float4* hp = (const float4*)(h + (size_t)node * heads * ch + hd * ch);
    const float4* sp = (const float4*)(att_s + hd * ch);
    const float4* dp = (const float4*)(att_d + hd * ch);
    float s = 0.f, d = 0.f;
    for (int c = 0; c < ch / 4; c++) {
        float4 v = hp[c], a = sp[c], b = dp[c];
        s += v.x * a.x + v.y * a.y + v.z * a.z + v.w * a.w;
        d += v.x * b.x + v.y * b.y + v.z * b.z + v.w * b.w;
    }
    asrc[i] = s; adst[i] = d;
}

// ---------------- fp32 -> bf16 convert (4 elems / thread) ----------------
__global__ void convert_kernel(const float* __restrict__ src, __nv_bfloat16* __restrict__ dst, int n4) {
    int i = blockIdx.x * blockDim.x + threadIdx.x;
    if (i >= n4) return;
    float4 v = *(const float4*)(src + (size_t)i * 4);
    __nv_bfloat162 lo = __floats2bfloat162_rn(v.x, v.y);
    __nv_bfloat162 hi = __floats2bfloat162_rn(v.z, v.w);
    uint2 out;
    out.x = *reinterpret_cast<unsigned*>(&lo);
    out.y = *reinterpret_cast<unsigned*>(&hi);
    *(uint2*)(dst + (size_t)i * 4) = out;
}

// ---------------- CSR aggregation: one warp per dst node, registers accumulate ----------------
// out[n,c] = relu( (1/(den+eps)) * sum_e exp(lrelu(asrc[s]+adst[n])) * hb[s,c] + bias[c] )
// POOL=false: write fp32 out[n*C+c].  POOL=true: atomicAdd into pool[batch[n]*C+c].
template <int H, int C, bool POOL>
__global__ __launch_bounds__(256) void agg_kernel(
    const __nv_bfloat16* __restrict__ hb,
    const float* __restrict__ asrc, const float* __restrict__ adst,
    const float* __restrict__ bias,
    const int* __restrict__ batch,
    float* __restrict__ outp)
{
    int n = (blockIdx.x * blockDim.x + threadIdx.x) >> 5;
    int lane = threadIdx.x & 31;
    if (n >= NN) return;

    constexpr int CPL = C / 32;          // 8 (C=256) or 4 (C=128)
    const int hd = (lane * CPL) / (C / H);

    const float adn = adst[n * H + hd];
    const int beg = g_indptr[n];
    const int end = g_indptr[n + 1];

    float acc[CPL];
#pragma unroll
    for (int j = 0; j < CPL; j++) acc[j] = 0.f;
    float den = 0.f;

    int i = beg;
    int s = (i < end) ? g_esrc[i] : 0;
    while (i < end) {
        int s_next = (i + 1 < end) ? g_esrc[i + 1] : 0;
        float a = asrc[s * H + hd];
        const __nv_bfloat16* hp = hb + (size_t)s * C + lane * CPL;
        float e = __expf(lrelu(a + adn));
        den += e;
        if (CPL == 8) {
            uint4 r = *(const uint4*)hp;
            float2 f0 = __bfloat1622float2(*reinterpret_cast<__nv_bfloat162*>(&r.x));
            float2 f1 = __bfloat1622float2(*reinterpret_cast<__nv_bfloat162*>(&r.y));
            float2 f2 = __bfloat1622float2(*reinterpret_cast<__nv_bfloat162*>(&r.z));
            float2 f3 = __bfloat1622float2(*reinterpret_cast<__nv_bfloat162*>(&r.w));
            acc[0] += e * f0.x; acc[1] += e * f0.y;
            acc[2] += e * f1.x; acc[3] += e * f1.y;
            acc[4] += e * f2.x; acc[5] += e * f2.y;
            acc[6] += e * f3.x; acc[7] += e * f3.y;
        } else {
            uint2 r = *(const uint2*)hp;
            float2 f0 = __bfloat1622float2(*reinterpret_cast<__nv_bfloat162*>(&r.x));
            float2 f1 = __bfloat1622float2(*reinterpret_cast<__nv_bfloat162*>(&r.y));
            acc[0] += e * f0.x; acc[1] += e * f0.y;
            acc[2] += e * f1.x; acc[3] += e * f1.y;
        }
        s = s_next;
        i++;
    }

    const float inv = 1.f / (den + EPSV);
    if (POOL) {
        int g = batch[n];
        float* pp = outp + (size_t)g * C + lane * CPL;
#pragma unroll
        for (int j = 0; j < CPL; j++) {
            float v = acc[j] * inv + bias[lane * CPL + j];
            v = v > 0.f ? v : 0.f;
            atomicAdd(pp + j, v);
        }
    } else {
        float* op = outp + (size_t)n * C + lane * CPL;
#pragma unroll
        for (int j = 0; j < CPL; j++) {
            float v = acc[j] * inv + bias[lane * CPL + j];
            acc[j] = v > 0.f ? v : 0.f;
        }
#pragma unroll
        for (int j = 0; j < CPL; j += 4)
            *(float4*)(op + j) = make_float4(acc[j], acc[j + 1], acc[j + 2], acc[j + 3]);
    }
}

// ---------------- node count per graph ----------------
__global__ void cnt_kernel(const int* __restrict__ batch) {
    int n = blockIdx.x * blockDim.x + threadIdx.x;
    if (n >= NN) return;
    atomicAdd(&g_cnt[batch[n]], 1.0f);
}

__global__ void pool_div_kernel(float* __restrict__ pool) {
    int i = blockIdx.x * blockDim.x + threadIdx.x;
    if (i >= NG * C2) return;
    int g = i >> 7;
    float c = g_cnt[g];
    pool[i] = pool[i] / (c > 1.f ? c : 1.f);
}

// ---------------- host launcher (graph-capturable, default stream) ----------------
extern "C" void kernel_launch(void* const* d_in, const int* in_sizes, int n_in,
                              void* d_out, int out_size)
{
    const float* x    = (const float*)d_in[0];
    const float* W1   = (const float*)d_in[1];
    const float* as1  = (const float*)d_in[2];
    const float* ad1  = (const float*)d_in[3];
    const float* b1   = (const float*)d_in[4];
    const float* W2   = (const float*)d_in[5];
    const float* as2  = (const float*)d_in[6];
    const float* ad2  = (const float*)d_in[7];
    const float* b2   = (const float*)d_in[8];
    const int*   ei   = (const int*)d_in[9];
    const int*   batch= (const int*)d_in[10];
    float* pool = (float*)d_out;

    float *p_h1, *p_out1, *p_h2;
    float *p_asrc1, *p_adst1, *p_asrc2, *p_adst2;
    __nv_bfloat16 *p_hb1, *p_hb2;
    cudaGetSymbolAddress((void**)&p_h1, g_h1);
    cudaGetSymbolAddress((void**)&p_out1, g_out1);
    cudaGetSymbolAddress((void**)&p_h2, g_h2);
    cudaGetSymbolAddress((void**)&p_hb1, g_hb1);
    cudaGetSymbolAddress((void**)&p_hb2, g_hb2);
    cudaGetSymbolAddress((void**)&p_asrc1, g_asrc1);
    cudaGetSymbolAddress((void**)&p_adst1, g_adst1);
    cudaGetSymbolAddress((void**)&p_asrc2, g_asrc2);
    cudaGetSymbolAddress((void**)&p_adst2, g_adst2);

    const int TB = 256;

    // 0) init (hist/pool/cnt)
    init_kernel<<<(NN + TB - 1) / TB, TB>>>(pool);
    // 1) CSR build (shared by both layers)
    hist_kernel<<<(ET + TB - 1) / TB, TB>>>(ei);
    scan_kernel<<<1, 1024>>>();
    scatter_kernel<<<(ET + TB - 1) / TB, TB>>>(ei);

    // 2) h1 = x @ W1
    {
        dim3 grid(C1 / 64, (NN + 63) / 64);
        sgemm_kernel<<<grid, 256>>>(x, W1, p_h1, NN, C1, 256);
    }
    // 3) attention scores layer 1 + bf16 convert
    attn_scores_kernel<<<(NN * H1 + TB - 1) / TB, TB>>>(p_h1, as1, ad1, p_asrc1, p_adst1, H1, CH1);
    convert_kernel<<<(NN * C1 / 4 + TB - 1) / TB, TB>>>(p_h1, p_hb1, NN * C1 / 4);
    // 4) CSR aggregation layer 1 (fused normalize+bias+relu) -> g_out1
    agg_kernel<H1, C1, false><<<(NN * 32 + TB - 1) / TB, TB>>>(
        p_hb1, p_asrc1, p_adst1, b1, batch, p_out1);

    // 5) h2 = out1 @ W2
    {
        dim3 grid(C2 / 64, (NN + 63) / 64);
        sgemm_kernel<<<grid, 256>>>(p_out1, W2, p_h2, NN, C2, 256);
    }
    // 6) attention scores layer 2 + bf16 convert
    attn_scores_kernel<<<(NN + TB - 1) / TB, TB>>>(p_h2, as2, ad2, p_asrc2, p_adst2, 1, C2);
    convert_kernel<<<(NN * C2 / 4 + TB - 1) / TB, TB>>>(p_h2, p_hb2, NN * C2 / 4);
    // 7) graph node counts
    cnt_kernel<<<(NN + TB - 1) / TB, TB>>>(batch);
    // 8) CSR aggregation layer 2, accumulate straight into pool
    agg_kernel<1, C2, true><<<(NN * 32 + TB - 1) / TB, TB>>>(
        p_hb2, p_asrc2, p_adst2, b2, batch, pool);
    // 9) mean
    pool_div_kernel<<<(NG * C2 + TB - 1) / TB, TB>>>(pool);
}

// round 11
// speedup vs baseline: 2.4332x; 1.2248x over previous
#include <cuda_runtime.h>
#include <cuda_bf16.h>
#include <cstdint>

#define NN 50000
#define NE 800000
#define ET 850000   // NE + NN self loops
#define NG 100
#define C1 256      // heads*hid = 4*64
#define H1 4
#define CH1 64
#define C2 128
#define NEG_SLOPE 0.2f
#define EPSV 1e-16f

// ---------------- scratch (device globals; no allocation allowed) ----------------
__device__ __align__(16) float g_h1[NN * C1];      // x @ W1 (fp32)
__device__ __align__(16) float g_out1[NN * C1];    // layer-1 final (fp32, GEMM2 input)
__device__ __align__(16) float g_h2[NN * C2];      // relu_out1 @ W2 (fp32)
__device__ __align__(16) __nv_bfloat16 g_hb1[NN * C1];  // bf16 copy of h1 for gather
__device__ __align__(16) __nv_bfloat16 g_hb2[NN * C2];  // bf16 copy of h2 for gather
__device__ __align__(16) float g_asrc1[NN * H1];
__device__ __align__(16) float g_adst1[NN * H1];
__device__ float g_asrc2[NN], g_adst2[NN];
__device__ float g_cnt[NG];
// CSR scratch
__device__ int g_hist[NN];
__device__ int g_indptr[NN + 1];
__device__ int g_off[NN];
__device__ int g_esrc[ET];

__device__ __forceinline__ float lrelu(float a) { return a > 0.f ? a : NEG_SLOPE * a; }
__device__ __forceinline__ float to_tf32(float x) {
    unsigned u;
    asm("cvt.rna.tf32.f32 %0, %1;" : "=r"(u) : "f"(x));
    return __uint_as_float(u);
}

// ---------------- init: zero histogram + pool + cnt ----------------
__global__ void init_kernel(float* __restrict__ pool) {
    int i = blockIdx.x * blockDim.x + threadIdx.x;
    if (i < NN)      g_hist[i] = 0;
    if (i < NG * C2) pool[i] = 0.f;
    if (i < NG)      g_cnt[i] = 0.f;
}

// ---------------- CSR build: histogram of dst ----------------
__global__ void hist_kernel(const int* __restrict__ ei) {
    int e = blockIdx.x * blockDim.x + threadIdx.x;
    if (e >= ET) return;
    int dn = (e < NE) ? ei[NE + e] : (e - NE);
    atomicAdd(&g_hist[dn], 1);
}

// ---------------- CSR build: exclusive scan (single block, sequential chunks) ----------------
__global__ void scan_kernel() {
    __shared__ int temp[1024];
    __shared__ int carry;
    const int t = threadIdx.x;
    if (t == 0) carry = 0;
    __syncthreads();
    for (int chunk = 0; chunk < NN; chunk += 1024) {
        int v = (chunk + t < NN) ? g_hist[chunk + t] : 0;
        temp[t] = v;
        __syncthreads();
        for (int d = 1; d < 1024; d <<= 1) {
            int x = (t >= d) ? temp[t - d] : 0;
            __syncthreads();
            temp[t] += x;
            __syncthreads();
        }
        int excl = temp[t] - v;
        if (chunk + t < NN) {
            g_indptr[chunk + t] = carry + excl;
            g_off[chunk + t]    = carry + excl;
        }
        __syncthreads();
        if (t == 1023) carry += temp[1023];
        __syncthreads();
    }
    if (t == 0) g_indptr[NN] = carry;
}

// ---------------- CSR build: scatter src ids grouped by dst ----------------
__global__ void scatter_kernel(const int* __restrict__ ei) {
    int e = blockIdx.x * blockDim.x + threadIdx.x;
    if (e >= ET) return;
    int s, dn;
    if (e < NE) { s = ei[e]; dn = ei[NE + e]; }
    else        { s = dn = e - NE; }
    int pos = atomicAdd(&g_off[dn], 1);
    g_esrc[pos] = s;
}

// ---------------- TF32 tensor-core GEMM: C[M,N] = A[M,K] @ B[K,N], row-major fp32 ----------------
// BM=128 BN=128 BK=16, 256 threads (8 warps, warp tile 64x32), mma.sync.m16n8k8.tf32.
// Smem: A as [m][k] stride 20, B transposed [n][k] stride 20 -> conflict-free fragment LDS.
// Requires N % 128 == 0, K % 16 == 0; M guarded.
__global__ __launch_bounds__(256) void gemm_tf32_kernel(
    const float* __restrict__ A, const float* __restrict__ B, float* __restrict__ C,
    int M, int N, int K)
{
    __shared__ __align__(16) float As[2][128][20];  // [buf][m][k]
    __shared__ __align__(16) float Bs[2][128][20];  // [buf][n][k]

    const int t    = threadIdx.x;
    const int lane = t & 31;
    const int wid  = t >> 5;
    const int g    = lane >> 2;   // 0..7
    const int tig  = lane & 3;    // 0..3
    const int wm   = (wid >> 2) * 64;  // 0 or 64
    const int wn   = (wid & 3) * 32;   // 0,32,64,96
    const int bm   = blockIdx.y * 128;
    const int bn   = blockIdx.x * 128;

    // A loader: rows t>>2 and (t>>2)+64, cols (t&3)*4
    const int ar = t >> 2;
    const int ac = (t & 3) * 4;
    // B loader: row t>>4 (k), cols (t&15)*8 .. +7 (n)
    const int brr = t >> 4;
    const int bcc = (t & 15) * 8;

    float acc[4][4][4];   // [mi][nj][reg]
#pragma unroll
    for (int i = 0; i < 4; i++)
#pragma unroll
        for (int j = 0; j < 4; j++)
#pragma unroll
            for (int r = 0; r < 4; r++) acc[i][j][r] = 0.f;

    const int NT = K / 16;
    float4 pa0, pa1, pb0, pb1;

    // load tile 0
    {
        pa0 = make_float4(0.f, 0.f, 0.f, 0.f); pa1 = pa0;
        if (bm + ar < M)      pa0 = *(const float4*)(A + (size_t)(bm + ar) * K + ac);
        if (bm + ar + 64 < M) pa1 = *(const float4*)(A + (size_t)(bm + ar + 64) * K + ac);
        pb0 = *(const float4*)(B + (size_t)brr * N + bn + bcc);
        pb1 = *(const float4*)(B + (size_t)brr * N + bn + bcc + 4);
        *(float4*)&As[0][ar][ac]      = make_float4(to_tf32(pa0.x), to_tf32(pa0.y), to_tf32(pa0.z), to_tf32(pa0.w));
        *(float4*)&As[0][ar + 64][ac] = make_float4(to_tf32(pa1.x), to_tf32(pa1.y), to_tf32(pa1.z), to_tf32(pa1.w));
        Bs[0][bcc + 0][brr] = to_tf32(pb0.x); Bs[0][bcc + 1][brr] = to_tf32(pb0.y);
        Bs[0][bcc + 2][brr] = to_tf32(pb0.z); Bs[0][bcc + 3][brr] = to_tf32(pb0.w);
        Bs[0][bcc + 4][brr] = to_tf32(pb1.x); Bs[0][bcc + 5][brr] = to_tf32(pb1.y);
        Bs[0][bcc + 6][brr] = to_tf32(pb1.z); Bs[0][bcc + 7][brr] = to_tf32(pb1.w);
    }
    __syncthreads();

    int buf = 0;
    for (int it = 0; it < NT; it++) {
        // prefetch next tile into registers
        if (it + 1 < NT) {
            int k0 = (it + 1) * 16;
            pa0 = make_float4(0.f, 0.f, 0.f, 0.f); pa1 = pa0;
            if (bm + ar < M)      pa0 = *(const float4*)(A + (size_t)(bm + ar) * K + k0 + ac);
            if (bm + ar + 64 < M) pa1 = *(const float4*)(A + (size_t)(bm + ar + 64) * K + k0 + ac);
            pb0 = *(const float4*)(B + (size_t)(k0 + brr) * N + bn + bcc);
            pb1 = *(const float4*)(B + (size_t)(k0 + brr) * N + bn + bcc + 4);
        }
        // compute on current buffer: 2 k-steps of 8
#pragma unroll
        for (int ks = 0; ks < 2; ks++) {
            const int kk = ks * 8;
            unsigned af[4][4], bf[4][2];
#pragma unroll
            for (int i = 0; i < 4; i++) {
                int r = wm + i * 16 + g;
                af[i][0] = __float_as_uint(As[buf][r][kk + tig]);
                af[i][1] = __float_as_uint(As[buf][r + 8][kk + tig]);
                af[i][2] = __float_as_uint(As[buf][r][kk + tig + 4]);
                af[i][3] = __float_as_uint(As[buf][r + 8][kk + tig + 4]);
            }
#pragma unroll
            for (int j = 0; j < 4; j++) {
                int n = wn + j * 8 + g;
                bf[j][0] = __float_as_uint(Bs[buf][n][kk + tig]);
                bf[j][1] = __float_as_uint(Bs[buf][n][kk + tig + 4]);
            }
#pragma unroll
            for (int i = 0; i < 4; i++)
#pragma unroll
                for (int j = 0; j < 4; j++) {
                    asm volatile(
                        "mma.sync.aligned.m16n8k8.row.col.f32.tf32.tf32.f32 "
                        "{%0,%1,%2,%3}, {%4,%5,%6,%7}, {%8,%9}, {%0,%1,%2,%3};"
                        : "+f"(acc[i][j][0]), "+f"(acc[i][j][1]),
                          "+f"(acc[i][j][2]), "+f"(acc[i][j][3])
                        : "r"(af[i][0]), "r"(af[i][1]), "r"(af[i][2]), "r"(af[i][3]),
                          "r"(bf[j][0]), "r"(bf[j][1]));
                }
        }
        // store prefetched tile into other buffer
        if (it + 1 < NT) {
            int nb = buf ^ 1;
            *(float4*)&As[nb][ar][ac]      = make_float4(to_tf32(pa0.x), to_tf32(pa0.y), to_tf32(pa0.z), to_tf32(pa0.w));
            *(float4*)&As[nb][ar + 64][ac] = make_float4(to_tf32(pa1.x), to_tf32(pa1.y), to_tf32(pa1.z), to_tf32(pa1.w));
            Bs[nb][bcc + 0][brr] = to_tf32(pb0.x); Bs[nb][bcc + 1][brr] = to_tf32(pb0.y);
            Bs[nb][bcc + 2][brr] = to_tf32(pb0.z); Bs[nb][bcc + 3][brr] = to_tf32(pb0.w);
            Bs[nb][bcc + 4][brr] = to_tf32(pb1.x); Bs[nb][bcc + 5][brr] = to_tf32(pb1.y);
            Bs[nb][bcc + 6][brr] = to_tf32(pb1.z); Bs[nb][bcc + 7][brr] = to_tf32(pb1.w);
        }
        __syncthreads();
        buf ^= 1;
    }

    // epilogue: c0/c1 -> (row, 2*tig), c2/c3 -> (row+8, 2*tig)
#pragma unroll
    for (int i = 0; i < 4; i++) {
#pragma unroll
        for (int j = 0; j < 4; j++) {
            int row = bm + wm + i * 16 + g;
            int col = bn + wn + j * 8 + 2 * tig;
            if (row < M)
                *(float2*)(C + (size_t)row * N + col) = make_float2(acc[i][j][0], acc[i][j][1]);
            if (row + 8 < M)
                *(float2*)(C + (size_t)(row + 8) * N + col) = make_float2(acc[i][j][2], acc[i][j][3]);
        }
    }
}

// ---------------- attention scores ----------------
__global__ void attn_scores_kernel(const float* __restrict__ h,
                                   const float* __restrict__ att_s,
                                   const float* __restrict__ att_d,
                                   float* __restrict__ asrc, float* __restrict__ adst,
                                   int heads, int ch)
{
    int i = blockIdx.x * blockDim.x + threadIdx.x;
    if (i >= NN * heads) return;
    int node = i / heads, hd = i - node * heads;
    const float4* hp = (const float4*)(h + (size_t)node * heads * ch + hd * ch);
    const float4* sp = (const float4*)(att_s + hd * ch);
    const float4* dp = (const float4*)(att_d + hd * ch);
    float s = 0.f, d = 0.f;
    for (int c = 0; c < ch / 4; c++) {
        float4 v = hp[c], a = sp[c], b = dp[c];
        s += v.x * a.x + v.y * a.y + v.z * a.z + v.w * a.w;
        d += v.x * b.x + v.y * b.y + v.z * b.z + v.w * b.w;
    }
    asrc[i] = s; adst[i] = d;
}

// ---------------- fp32 -> bf16 convert (4 elems / thread) ----------------
__global__ void convert_kernel(const float* __restrict__ src, __nv_bfloat16* __restrict__ dst, int n4) {
    int i = blockIdx.x * blockDim.x + threadIdx.x;
    if (i >= n4) return;
    float4 v = *(const float4*)(src + (size_t)i * 4);
    __nv_bfloat162 lo = __floats2bfloat162_rn(v.x, v.y);
    __nv_bfloat162 hi = __floats2bfloat162_rn(v.z, v.w);
    uint2 out;
    out.x = *reinterpret_cast<unsigned*>(&lo);
    out.y = *reinterpret_cast<unsigned*>(&hi);
    *(uint2*)(dst + (size_t)i * 4) = out;
}

// ---------------- CSR aggregation: one warp per dst node, registers accumulate ----------------
template <int H, int C, bool POOL>
__global__ __launch_bounds__(256) void agg_kernel(
    const __nv_bfloat16* __restrict__ hb,
    const float* __restrict__ asrc, const float* __restrict__ adst,
    const float* __restrict__ bias,
    const int* __restrict__ batch,
    float* __restrict__ outp)
{
    int n = (blockIdx.x * blockDim.x + threadIdx.x) >> 5;
    int lane = threadIdx.x & 31;
    if (n >= NN) return;

    constexpr int CPL = C / 32;          // 8 (C=256) or 4 (C=128)
    const int hd = (lane * CPL) / (C / H);

    const float adn = adst[n * H + hd];
    const int beg = g_indptr[n];
    const int end = g_indptr[n + 1];

    float acc[CPL];
#pragma unroll
    for (int j = 0; j < CPL; j++) acc[j] = 0.f;
    float den = 0.f;

    int i = beg;
    int s = (i < end) ? g_esrc[i] : 0;
    while (i < end) {
        int s_next = (i + 1 < end) ? g_esrc[i + 1] : 0;
        float a = asrc[s * H + hd];
        const __nv_bfloat16* hp = hb + (size_t)s * C + lane * CPL;
        float e = __expf(lrelu(a + adn));
        den += e;
        if (CPL == 8) {
            uint4 r = *(const uint4*)hp;
            float2 f0 = __bfloat1622float2(*reinterpret_cast<__nv_bfloat162*>(&r.x));
            float2 f1 = __bfloat1622float2(*reinterpret_cast<__nv_bfloat162*>(&r.y));
            float2 f2 = __bfloat1622float2(*reinterpret_cast<__nv_bfloat162*>(&r.z));
            float2 f3 = __bfloat1622float2(*reinterpret_cast<__nv_bfloat162*>(&r.w));
            acc[0] += e * f0.x; acc[1] += e * f0.y;
            acc[2] += e * f1.x; acc[3] += e * f1.y;
            acc[4] += e * f2.x; acc[5] += e * f2.y;
            acc[6] += e * f3.x; acc[7] += e * f3.y;
        } else {
            uint2 r = *(const uint2*)hp;
            float2 f0 = __bfloat1622float2(*reinterpret_cast<__nv_bfloat162*>(&r.x));
            float2 f1 = __bfloat1622float2(*reinterpret_cast<__nv_bfloat162*>(&r.y));
            acc[0] += e * f0.x; acc[1] += e * f0.y;
            acc[2] += e * f1.x; acc[3] += e * f1.y;
        }
        s = s_next;
        i++;
    }

    const float inv = 1.f / (den + EPSV);
    if (POOL) {
        int g = batch[n];
        float* pp = outp + (size_t)g * C + lane * CPL;
#pragma unroll
        for (int j = 0; j < CPL; j++) {
            float v = acc[j] * inv + bias[lane * CPL + j];
            v = v > 0.f ? v : 0.f;
            atomicAdd(pp + j, v);
        }
    } else {
        float* op = outp + (size_t)n * C + lane * CPL;
#pragma unroll
        for (int j = 0; j < CPL; j++) {
            float v = acc[j] * inv + bias[lane * CPL + j];
            acc[j] = v > 0.f ? v : 0.f;
        }
#pragma unroll
        for (int j = 0; j < CPL; j += 4)
            *(float4*)(op + j) = make_float4(acc[j], acc[j + 1], acc[j + 2], acc[j + 3]);
    }
}

// ---------------- node count per graph ----------------
__global__ void cnt_kernel(const int* __restrict__ batch) {
    int n = blockIdx.x * blockDim.x + threadIdx.x;
    if (n >= NN) return;
    atomicAdd(&g_cnt[batch[n]], 1.0f);
}

__global__ void pool_div_kernel(float* __restrict__ pool) {
    int i = blockIdx.x * blockDim.x + threadIdx.x;
    if (i >= NG * C2) return;
    int g = i >> 7;
    float c = g_cnt[g];
    pool[i] = pool[i] / (c > 1.f ? c : 1.f);
}

// ---------------- host launcher (graph-capturable, default stream) ----------------
extern "C" void kernel_launch(void* const* d_in, const int* in_sizes, int n_in,
                              void* d_out, int out_size)
{
    const float* x    = (const float*)d_in[0];
    const float* W1   = (const float*)d_in[1];
    const float* as1  = (const float*)d_in[2];
    const float* ad1  = (const float*)d_in[3];
    const float* b1   = (const float*)d_in[4];
    const float* W2   = (const float*)d_in[5];
    const float* as2  = (const float*)d_in[6];
    const float* ad2  = (const float*)d_in[7];
    const float* b2   = (const float*)d_in[8];
    const int*   ei   = (const int*)d_in[9];
    const int*   batch= (const int*)d_in[10];
    float* pool = (float*)d_out;

    float *p_h1, *p_out1, *p_h2;
    float *p_asrc1, *p_adst1, *p_asrc2, *p_adst2;
    __nv_bfloat16 *p_hb1, *p_hb2;
    cudaGetSymbolAddress((void**)&p_h1, g_h1);
    cudaGetSymbolAddress((void**)&p_out1, g_out1);
    cudaGetSymbolAddress((void**)&p_h2, g_h2);
    cudaGetSymbolAddress((void**)&p_hb1, g_hb1);
    cudaGetSymbolAddress((void**)&p_hb2, g_hb2);
    cudaGetSymbolAddress((void**)&p_asrc1, g_asrc1);
    cudaGetSymbolAddress((void**)&p_adst1, g_adst1);
    cudaGetSymbolAddress((void**)&p_asrc2, g_asrc2);
    cudaGetSymbolAddress((void**)&p_adst2, g_adst2);

    const int TB = 256;

    // 0) init (hist/pool/cnt)
    init_kernel<<<(NN + TB - 1) / TB, TB>>>(pool);
    // 1) CSR build (shared by both layers)
    hist_kernel<<<(ET + TB - 1) / TB, TB>>>(ei);
    scan_kernel<<<1, 1024>>>();
    scatter_kernel<<<(ET + TB - 1) / TB, TB>>>(ei);

    // 2) h1 = x @ W1  (tf32 tensor cores)
    {
        dim3 grid(C1 / 128, (NN + 127) / 128);
        gemm_tf32_kernel<<<grid, 256>>>(x, W1, p_h1, NN, C1, 256);
    }
    // 3) attention scores layer 1 + bf16 convert
    attn_scores_kernel<<<(NN * H1 + TB - 1) / TB, TB>>>(p_h1, as1, ad1, p_asrc1, p_adst1, H1, CH1);
    convert_kernel<<<(NN * C1 / 4 + TB - 1) / TB, TB>>>(p_h1, p_hb1, NN * C1 / 4);
    // 4) CSR aggregation layer 1 (fused normalize+bias+relu) -> g_out1
    agg_kernel<H1, C1, false><<<(NN * 32 + TB - 1) / TB, TB>>>(
        p_hb1, p_asrc1, p_adst1, b1, batch, p_out1);

    // 5) h2 = out1 @ W2  (tf32 tensor cores)
    {
        dim3 grid(C2 / 128, (NN + 127) / 128);
        gemm_tf32_kernel<<<grid, 256>>>(p_out1, W2, p_h2, NN, C2, 256);
    }
    // 6) attention scores layer 2 + bf16 convert
    attn_scores_kernel<<<(NN + TB - 1) / TB, TB>>>(p_h2, as2, ad2, p_asrc2, p_adst2, 1, C2);
    convert_kernel<<<(NN * C2 / 4 + TB - 1) / TB, TB>>>(p_h2, p_hb2, NN * C2 / 4);
    // 7) graph node counts
    cnt_kernel<<<(NN + TB - 1) / TB, TB>>>(batch);
    // 8) CSR aggregation layer 2, accumulate straight into pool
    agg_kernel<1, C2, true><<<(NN * 32 + TB - 1) / TB, TB>>>(
        p_hb2, p_asrc2, p_adst2, b2, batch, pool);
    // 9) mean
    pool_div_kernel<<<(NG * C2 + TB - 1) / TB, TB>>>(pool);
}

// round 13
// speedup vs baseline: 2.4489x; 1.0065x over previous
#include <cuda_runtime.h>
#include <cuda_bf16.h>
#include <cstdint>

#define NN 50000
#define NE 800000
#define ET 850000   // NE + NN self loops
#define NG 100
#define C1 256      // heads*hid = 4*64
#define H1 4
#define CH1 64
#define C2 128
#define NEG_SLOPE 0.2f
#define EPSV 1e-16f

// ---------------- scratch (device globals; no allocation allowed) ----------------
__device__ __align__(16) float g_h1[NN * C1];      // x @ W1 (fp32)
__device__ __align__(16) float g_out1[NN * C1];    // layer-1 final (fp32, GEMM2 input)
__device__ __align__(16) float g_h2[NN * C2];      // relu_out1 @ W2 (fp32)
__device__ __align__(16) __nv_bfloat16 g_hb1[NN * C1];  // bf16 copy of h1 for gather
__device__ __align__(16) __nv_bfloat16 g_hb2[NN * C2];  // bf16 copy of h2 for gather
__device__ __align__(16) float g_asrc1[NN * H1];
__device__ __align__(16) float g_adst1[NN * H1];
__device__ float g_asrc2[NN], g_adst2[NN];
__device__ float g_cnt[NG];
// CSR scratch
__device__ int g_hist[NN];
__device__ int g_indptr[NN + 1];
__device__ int g_off[NN];
__device__ int g_esrc[ET];

__device__ __forceinline__ float lrelu(float a) { return a > 0.f ? a : NEG_SLOPE * a; }
__device__ __forceinline__ float to_tf32(float x) {
    unsigned u;
    asm("cvt.rna.tf32.f32 %0, %1;" : "=r"(u) : "f"(x));
    return __uint_as_float(u);
}

// ---------------- init: zero histogram + pool + cnt ----------------
__global__ void init_kernel(float* __restrict__ pool) {
    int i = blockIdx.x * blockDim.x + threadIdx.x;
    if (i < NN)      g_hist[i] = 0;
    if (i < NG * C2) pool[i] = 0.f;
    if (i < NG)      g_cnt[i] = 0.f;
}

// ---------------- CSR build: histogram of dst ----------------
__global__ void hist_kernel(const int* __restrict__ ei) {
    int e = blockIdx.x * blockDim.x + threadIdx.x;
    if (e >= ET) return;
    int dn = (e < NE) ? ei[NE + e] : (e - NE);
    atomicAdd(&g_hist[dn], 1);
}

// ---------------- CSR build: exclusive scan, thread-serial chunks + warp-shuffle block scan ----------------
__global__ void scan_kernel() {   // launch with 1024 threads, 1 block
    __shared__ int warp_sums[32];
    const int t = threadIdx.x;
    const int PER = (NN + 1023) / 1024;   // 49
    const int base = t * PER;

    int sum = 0;
    for (int j = 0; j < PER; j++) {
        int idx = base + j;
        if (idx < NN) sum += g_hist[idx];
    }
    // block exclusive scan of per-thread sums
    const int lane = t & 31, wid = t >> 5;
    int v = sum;
#pragma unroll
    for (int d = 1; d < 32; d <<= 1) {
        int x = __shfl_up_sync(0xffffffffu, v, d);
        if (lane >= d) v += x;
    }
    if (lane == 31) warp_sums[wid] = v;
    __syncthreads();
    if (wid == 0) {
        int w = warp_sums[lane];
#pragma unroll
        for (int d = 1; d < 32; d <<= 1) {
            int x = __shfl_up_sync(0xffffffffu, w, d);
            if (lane >= d) w += x;
        }
        warp_sums[lane] = w;
    }
    __syncthreads();
    int running = (v - sum) + (wid > 0 ? warp_sums[wid - 1] : 0);
    for (int j = 0; j < PER; j++) {
        int idx = base + j;
        if (idx < NN) {
            g_indptr[idx] = running;
            g_off[idx]    = running;
            running += g_hist[idx];
        }
    }
    if (t == 1023) g_indptr[NN] = running;
}

// ---------------- CSR build: scatter src ids grouped by dst ----------------
__global__ void scatter_kernel(const int* __restrict__ ei) {
    int e = blockIdx.x * blockDim.x + threadIdx.x;
    if (e >= ET) return;
    int s, dn;
    if (e < NE) { s = ei[e]; dn = ei[NE + e]; }
    else        { s = dn = e - NE; }
    int pos = atomicAdd(&g_off[dn], 1);
    g_esrc[pos] = s;
}

// ---------------- TF32 tensor-core GEMM: C[M,N] = A[M,K] @ B[K,N], row-major fp32 ----------------
// Also writes bf16 copy Cb (for the gather phase) straight from registers.
// BM=128 BN=128 BK=16, 256 threads (8 warps, warp tile 64x32), mma.sync.m16n8k8.tf32.
__global__ __launch_bounds__(256) void gemm_tf32_kernel(
    const float* __restrict__ A, const float* __restrict__ B,
    float* __restrict__ C, __nv_bfloat16* __restrict__ Cb,
    int M, int N, int K)
{
    __shared__ __align__(16) float As[2][128][20];  // [buf][m][k]
    __shared__ __align__(16) float Bs[2][128][20];  // [buf][n][k]

    const int t    = threadIdx.x;
    const int lane = t & 31;
    const int wid  = t >> 5;
    const int g    = lane >> 2;   // 0..7
    const int tig  = lane & 3;    // 0..3
    const int wm   = (wid >> 2) * 64;  // 0 or 64
    const int wn   = (wid & 3) * 32;   // 0,32,64,96
    const int bm   = blockIdx.y * 128;
    const int bn   = blockIdx.x * 128;

    const int ar = t >> 2;
    const int ac = (t & 3) * 4;
    const int brr = t >> 4;
    const int bcc = (t & 15) * 8;

    float acc[4][4][4];
#pragma unroll
    for (int i = 0; i < 4; i++)
#pragma unroll
        for (int j = 0; j < 4; j++)
#pragma unroll
            for (int r = 0; r < 4; r++) acc[i][j][r] = 0.f;

    const int NT = K / 16;
    float4 pa0, pa1, pb0, pb1;

    {
        pa0 = make_float4(0.f, 0.f, 0.f, 0.f); pa1 = pa0;
        if (bm + ar < M)      pa0 = *(const float4*)(A + (size_t)(bm + ar) * K + ac);
        if (bm + ar + 64 < M) pa1 = *(const float4*)(A + (size_t)(bm + ar + 64) * K + ac);
        pb0 = *(const float4*)(B + (size_t)brr * N + bn + bcc);
        pb1 = *(const float4*)(B + (size_t)brr * N + bn + bcc + 4);
        *(float4*)&As[0][ar][ac]      = make_float4(to_tf32(pa0.x), to_tf32(pa0.y), to_tf32(pa0.z), to_tf32(pa0.w));
        *(float4*)&As[0][ar + 64][ac] = make_float4(to_tf32(pa1.x), to_tf32(pa1.y), to_tf32(pa1.z), to_tf32(pa1.w));
        Bs[0][bcc + 0][brr] = to_tf32(pb0.x); Bs[0][bcc + 1][brr] = to_tf32(pb0.y);
        Bs[0][bcc + 2][brr] = to_tf32(pb0.z); Bs[0][bcc + 3][brr] = to_tf32(pb0.w);
        Bs[0][bcc + 4][brr] = to_tf32(pb1.x); Bs[0][bcc + 5][brr] = to_tf32(pb1.y);
        Bs[0][bcc + 6][brr] = to_tf32(pb1.z); Bs[0][bcc + 7][brr] = to_tf32(pb1.w);
    }
    __syncthreads();

    int buf = 0;
    for (int it = 0; it < NT; it++) {
        if (it + 1 < NT) {
            int k0 = (it + 1) * 16;
            pa0 = make_float4(0.f, 0.f, 0.f, 0.f); pa1 = pa0;
            if (bm + ar < M)      pa0 = *(const float4*)(A + (size_t)(bm + ar) * K + k0 + ac);
            if (bm + ar + 64 < M) pa1 = *(const float4*)(A + (size_t)(bm + ar + 64) * K + k0 + ac);
            pb0 = *(const float4*)(B + (size_t)(k0 + brr) * N + bn + bcc);
            pb1 = *(const float4*)(B + (size_t)(k0 + brr) * N + bn + bcc + 4);
        }
#pragma unroll
        for (int ks = 0; ks < 2; ks++) {
            const int kk = ks * 8;
            unsigned af[4][4], bf[4][2];
#pragma unroll
            for (int i = 0; i < 4; i++) {
                int r = wm + i * 16 + g;
                af[i][0] = __float_as_uint(As[buf][r][kk + tig]);
                af[i][1] = __float_as_uint(As[buf][r + 8][kk + tig]);
                af[i][2] = __float_as_uint(As[buf][r][kk + tig + 4]);
                af[i][3] = __float_as_uint(As[buf][r + 8][kk + tig + 4]);
            }
#pragma unroll
            for (int j = 0; j < 4; j++) {
                int n = wn + j * 8 + g;
                bf[j][0] = __float_as_uint(Bs[buf][n][kk + tig]);
                bf[j][1] = __float_as_uint(Bs[buf][n][kk + tig + 4]);
            }
#pragma unroll
            for (int i = 0; i < 4; i++)
#pragma unroll
                for (int j = 0; j < 4; j++) {
                    asm volatile(
                        "mma.sync.aligned.m16n8k8.row.col.f32.tf32.tf32.f32 "
                        "{%0,%1,%2,%3}, {%4,%5,%6,%7}, {%8,%9}, {%0,%1,%2,%3};"
                        : "+f"(acc[i][j][0]), "+f"(acc[i][j][1]),
                          "+f"(acc[i][j][2]), "+f"(acc[i][j][3])
                        : "r"(af[i][0]), "r"(af[i][1]), "r"(af[i][2]), "r"(af[i][3]),
                          "r"(bf[j][0]), "r"(bf[j][1]));
                }
        }
        if (it + 1 < NT) {
            int nb = buf ^ 1;
            *(float4*)&As[nb][ar][ac]      = make_float4(to_tf32(pa0.x), to_tf32(pa0.y), to_tf32(pa0.z), to_tf32(pa0.w));
            *(float4*)&As[nb][ar + 64][ac] = make_float4(to_tf32(pa1.x), to_tf32(pa1.y), to_tf32(pa1.z), to_tf32(pa1.w));
            Bs[nb][bcc + 0][brr] = to_tf32(pb0.x); Bs[nb][bcc + 1][brr] = to_tf32(pb0.y);
            Bs[nb][bcc + 2][brr] = to_tf32(pb0.z); Bs[nb][bcc + 3][brr] = to_tf32(pb0.w);
            Bs[nb][bcc + 4][brr] = to_tf32(pb1.x); Bs[nb][bcc + 5][brr] = to_tf32(pb1.y);
            Bs[nb][bcc + 6][brr] = to_tf32(pb1.z); Bs[nb][bcc + 7][brr] = to_tf32(pb1.w);
        }
        __syncthreads();
        buf ^= 1;
    }

    // epilogue: fp32 + bf16 writes
#pragma unroll
    for (int i = 0; i < 4; i++) {
#pragma unroll
        for (int j = 0; j < 4; j++) {
            int row = bm + wm + i * 16 + g;
            int col = bn + wn + j * 8 + 2 * tig;
            if (row < M) {
                *(float2*)(C + (size_t)row * N + col) = make_float2(acc[i][j][0], acc[i][j][1]);
                __nv_bfloat162 bb = __floats2bfloat162_rn(acc[i][j][0], acc[i][j][1]);
                *(unsigned*)(Cb + (size_t)row * N + col) = *reinterpret_cast<unsigned*>(&bb);
            }
            if (row + 8 < M) {
                *(float2*)(C + (size_t)(row + 8) * N + col) = make_float2(acc[i][j][2], acc[i][j][3]);
                __nv_bfloat162 bb = __floats2bfloat162_rn(acc[i][j][2], acc[i][j][3]);
                *(unsigned*)(Cb + (size_t)(row + 8) * N + col) = *reinterpret_cast<unsigned*>(&bb);
            }
        }
    }
}

// ---------------- attention scores ----------------
__global__ void attn_scores_kernel(const float* __restrict__ h,
                                   const float* __restrict__ att_s,
                                   const float* __restrict__ att_d,
                                   float* __restrict__ asrc, float* __restrict__ adst,
                                   int heads, int ch)
{
    int i = blockIdx.x * blockDim.x + threadIdx.x;
    if (i >= NN * heads) return;
    int node = i / heads, hd = i - node * heads;
    const float4* hp = (const float4*)(h + (size_t)node * heads * ch + hd * ch);
    const float4* sp = (const float4*)(att_s + hd * ch);
    const float4* dp = (const float4*)(att_d + hd * ch);
    float s = 0.f, d = 0.f;
    for (int c = 0; c < ch / 4; c++) {
        float4 v = hp[c], a = sp[c], b = dp[c];
        s += v.x * a.x + v.y * a.y + v.z * a.z + v.w * a.w;
        d += v.x * b.x + v.y * b.y + v.z * b.z + v.w * b.w;
    }
    asrc[i] = s; adst[i] = d;
}

// ---------------- CSR aggregation: one warp per dst node, 4-wide edge unroll ----------------
template <int H, int C, bool POOL>
__global__ __launch_bounds__(256) void agg_kernel(
    const __nv_bfloat16* __restrict__ hb,
    const float* __restrict__ asrc, const float* __restrict__ adst,
    const float* __restrict__ bias,
    const int* __restrict__ batch,
    float* __restrict__ outp)
{
    int n = (blockIdx.x * blockDim.x + threadIdx.x) >> 5;
    int lane = threadIdx.x & 31;
    if (n >= NN) return;

    constexpr int CPL = C / 32;          // 8 (C=256) or 4 (C=128)
    const int hd = (lane * CPL) / (C / H);

    const float adn = adst[n * H + hd];
    const int beg = g_indptr[n];
    const int end = g_indptr[n + 1];

    float acc[CPL];
#pragma unroll
    for (int j = 0; j < CPL; j++) acc[j] = 0.f;
    float den = 0.f;

    const int laneoff = lane * CPL;
    int i = beg;

    // 4-wide unrolled main loop: 4 independent gathers in flight
    for (; i + 3 < end; i += 4) {
        int s0 = g_esrc[i], s1 = g_esrc[i + 1], s2 = g_esrc[i + 2], s3 = g_esrc[i + 3];
        float a0 = asrc[s0 * H + hd], a1 = asrc[s1 * H + hd];
        float a2 = asrc[s2 * H + hd], a3 = asrc[s3 * H + hd];
        if (CPL == 8) {
            uint4 r0 = *(const uint4*)(hb + (size_t)s0 * C + laneoff);
            uint4 r1 = *(const uint4*)(hb + (size_t)s1 * C + laneoff);
            uint4 r2 = *(const uint4*)(hb + (size_t)s2 * C + laneoff);
            uint4 r3 = *(const uint4*)(hb + (size_t)s3 * C + laneoff);
            float e0 = __expf(lrelu(a0 + adn)), e1 = __expf(lrelu(a1 + adn));
            float e2 = __expf(lrelu(a2 + adn)), e3 = __expf(lrelu(a3 + adn));
            den += (e0 + e1) + (e2 + e3);
            const uint4* rr[4] = {&r0, &r1, &r2, &r3};
            float ee[4] = {e0, e1, e2, e3};
#pragma unroll
            for (int q = 0; q < 4; q++) {
                float2 f0 = __bfloat1622float2(*reinterpret_cast<const __nv_bfloat162*>(&rr[q]->x));
                float2 f1 = __bfloat1622float2(*reinterpret_cast<const __nv_bfloat162*>(&rr[q]->y));
                float2 f2 = __bfloat1622float2(*reinterpret_cast<const __nv_bfloat162*>(&rr[q]->z));
                float2 f3 = __bfloat1622float2(*reinterpret_cast<const __nv_bfloat162*>(&rr[q]->w));
                float e = ee[q];
                acc[0] += e * f0.x; acc[1] += e * f0.y;
                acc[2] += e * f1.x; acc[3] += e * f1.y;
                acc[4] += e * f2.x; acc[5] += e * f2.y;
                acc[6] += e * f3.x; acc[7] += e * f3.y;
            }
        } else {
            uint2 r0 = *(const uint2*)(hb + (size_t)s0 * C + laneoff);
            uint2 r1 = *(const uint2*)(hb + (size_t)s1 * C + laneoff);
            uint2 r2 = *(const uint2*)(hb + (size_t)s2 * C + laneoff);
            uint2 r3 = *(const uint2*)(hb + (size_t)s3 * C + laneoff);
            float e0 = __expf(lrelu(a0 + adn)), e1 = __expf(lrelu(a1 + adn));
            float e2 = __expf(lrelu(a2 + adn)), e3 = __expf(lrelu(a3 + adn));
            den += (e0 + e1) + (e2 + e3);
            const uint2* rr[4] = {&r0, &r1, &r2, &r3};
            float ee[4] = {e0, e1, e2, e3};
#pragma unroll
            for (int q = 0; q < 4; q++) {
                float2 f0 = __bfloat1622float2(*reinterpret_cast<const __nv_bfloat162*>(&rr[q]->x));
                float2 f1 = __bfloat1622float2(*reinterpret_cast<const __nv_bfloat162*>(&rr[q]->y));
                float e = ee[q];
                acc[0] += e * f0.x; acc[1] += e * f0.y;
                acc[2] += e * f1.x; acc[3] += e * f1.y;
            }
        }
    }
    // remainder
    for (; i < end; i++) {
        int s = g_esrc[i];
        float a = asrc[s * H + hd];
        float e = __expf(lrelu(a + adn));
        den += e;
        const __nv_bfloat16* hp = hb + (size_t)s * C + laneoff;
        if (CPL == 8) {
            uint4 r = *(const uint4*)hp;
            float2 f0 = __bfloat1622float2(*reinterpret_cast<__nv_bfloat162*>(&r.x));
            float2 f1 = __bfloat1622float2(*reinterpret_cast<__nv_bfloat162*>(&r.y));
            float2 f2 = __bfloat1622float2(*reinterpret_cast<__nv_bfloat162*>(&r.z));
            float2 f3 = __bfloat1622float2(*reinterpret_cast<__nv_bfloat162*>(&r.w));
            acc[0] += e * f0.x; acc[1] += e * f0.y;
            acc[2] += e * f1.x; acc[3] += e * f1.y;
            acc[4] += e * f2.x; acc[5] += e * f2.y;
            acc[6] += e * f3.x; acc[7] += e * f3.y;
        } else {
            uint2 r = *(const uint2*)hp;
            float2 f0 = __bfloat1622float2(*reinterpret_cast<__nv_bfloat162*>(&r.x));
            float2 f1 = __bfloat1622float2(*reinterpret_cast<__nv_bfloat162*>(&r.y));
            acc[0] += e * f0.x; acc[1] += e * f0.y;
            acc[2] += e * f1.x; acc[3] += e * f1.y;
        }
    }

    const float inv = 1.f / (den + EPSV);
    if (POOL) {
        int g = batch[n];
        float* pp = outp + (size_t)g * C + laneoff;
#pragma unroll
        for (int j = 0; j < CPL; j++) {
            float v = acc[j] * inv + bias[laneoff + j];
            v = v > 0.f ? v : 0.f;
            atomicAdd(pp + j, v);
        }
    } else {
        float* op = outp + (size_t)n * C + laneoff;
#pragma unroll
        for (int j = 0; j < CPL; j++) {
            float v = acc[j] * inv + bias[laneoff + j];
            acc[j] = v > 0.f ? v : 0.f;
        }
#pragma unroll
        for (int j = 0; j < CPL; j += 4)
            *(float4*)(op + j) = make_float4(acc[j], acc[j + 1], acc[j + 2], acc[j + 3]);
    }
}

// ---------------- node count per graph ----------------
__global__ void cnt_kernel(const int* __restrict__ batch) {
    int n = blockIdx.x * blockDim.x + threadIdx.x;
    if (n >= NN) return;
    atomicAdd(&g_cnt[batch[n]], 1.0f);
}

__global__ void pool_div_kernel(float* __restrict__ pool) {
    int i = blockIdx.x * blockDim.x + threadIdx.x;
    if (i >= NG * C2) return;
    int g = i >> 7;
    float c = g_cnt[g];
    pool[i] = pool[i] / (c > 1.f ? c : 1.f);
}

// ---------------- host launcher (graph-capturable, default stream) ----------------
extern "C" void kernel_launch(void* const* d_in, const int* in_sizes, int n_in,
                              void* d_out, int out_size)
{
    const float* x    = (const float*)d_in[0];
    const float* W1   = (const float*)d_in[1];
    const float* as1  = (const float*)d_in[2];
    const float* ad1  = (const float*)d_in[3];
    const float* b1   = (const float*)d_in[4];
    const float* W2   = (const float*)d_in[5];
    const float* as2  = (const float*)d_in[6];
    const float* ad2  = (const float*)d_in[7];
    const float* b2   = (const float*)d_in[8];
    const int*   ei   = (const int*)d_in[9];
    const int*   batch= (const int*)d_in[10];
    float* pool = (float*)d_out;

    float *p_h1, *p_out1, *p_h2;
    float *p_asrc1, *p_adst1, *p_asrc2, *p_adst2;
    __nv_bfloat16 *p_hb1, *p_hb2;
    cudaGetSymbolAddress((void**)&p_h1, g_h1);
    cudaGetSymbolAddress((void**)&p_out1, g_out1);
    cudaGetSymbolAddress((void**)&p_h2, g_h2);
    cudaGetSymbolAddress((void**)&p_hb1, g_hb1);
    cudaGetSymbolAddress((void**)&p_hb2, g_hb2);
    cudaGetSymbolAddress((void**)&p_asrc1, g_asrc1);
    cudaGetSymbolAddress((void**)&p_adst1, g_adst1);
    cudaGetSymbolAddress((void**)&p_asrc2, g_asrc2);
    cudaGetSymbolAddress((void**)&p_adst2, g_adst2);

    const int TB = 256;

    // 0) init (hist/pool/cnt)
    init_kernel<<<(NN + TB - 1) / TB, TB>>>(pool);
    // 1) CSR build (shared by both layers)
    hist_kernel<<<(ET + TB - 1) / TB, TB>>>(ei);
    scan_kernel<<<1, 1024>>>();
    scatter_kernel<<<(ET + TB - 1) / TB, TB>>>(ei);

    // 2) h1 = x @ W1  (tf32 tensor cores, fused bf16 epilogue)
    {
        dim3 grid(C1 / 128, (NN + 127) / 128);
        gemm_tf32_kernel<<<grid, 256>>>(x, W1, p_h1, p_hb1, NN, C1, 256);
    }
    // 3) attention scores layer 1
    attn_scores_kernel<<<(NN * H1 + TB - 1) / TB, TB>>>(p_h1, as1, ad1, p_asrc1, p_adst1, H1, CH1);
    // 4) CSR aggregation layer 1 (fused normalize+bias+relu) -> g_out1
    agg_kernel<H1, C1, false><<<(NN * 32 + TB - 1) / TB, TB>>>(
        p_hb1, p_asrc1, p_adst1, b1, batch, p_out1);

    // 5) h2 = out1 @ W2  (tf32 tensor cores, fused bf16 epilogue)
    {
        dim3 grid(C2 / 128, (NN + 127) / 128);
        gemm_tf32_kernel<<<grid, 256>>>(p_out1, W2, p_h2, p_hb2, NN, C2, 256);
    }
    // 6) attention scores layer 2
    attn_scores_kernel<<<(NN + TB - 1) / TB, TB>>>(p_h2, as2, ad2, p_asrc2, p_adst2, 1, C2);
    // 7) graph node counts
    cnt_kernel<<<(NN + TB - 1) / TB, TB>>>(batch);
    // 8) CSR aggregation layer 2, accumulate straight into pool
    agg_kernel<1, C2, true><<<(NN * 32 + TB - 1) / TB, TB>>>(
        p_hb2, p_asrc2, p_adst2, b2, batch, pool);
    // 9) mean
    pool_div_kernel<<<(NG * C2 + TB - 1) / TB, TB>>>(pool);
}

// round 15
// speedup vs baseline: 2.4500x; 1.0004x over previous
#include <cuda_runtime.h>
#include <cuda_bf16.h>
#include <cstdint>

#define NN 50000
#define NE 800000
#define ET 850000   // NE + NN self loops
#define NG 100
#define C1 256      // heads*hid = 4*64
#define H1 4
#define CH1 64
#define C2 128
#define NEG_SLOPE 0.2f
#define EPSV 1e-16f

// ---------------- scratch (device globals; no allocation allowed) ----------------
__device__ __align__(16) float g_h1[NN * C1];      // x @ W1 (fp32)
__device__ __align__(16) float g_out1[NN * C1];    // layer-1 final (fp32, GEMM2 input)
__device__ __align__(16) float g_h2[NN * C2];      // relu_out1 @ W2 (fp32)
__device__ __align__(16) __nv_bfloat16 g_hb1[NN * C1];  // bf16 copy of h1 for gather
__device__ __align__(16) __nv_bfloat16 g_hb2[NN * C2];  // bf16 copy of h2 for gather
__device__ __align__(16) float g_asrc1[NN * H1];
__device__ __align__(16) float g_adst1[NN * H1];
__device__ float g_asrc2[NN], g_adst2[NN];
__device__ float g_cnt[NG];
// CSR scratch
__device__ int g_hist[NN];
__device__ int g_indptr[NN + 1];
__device__ int g_off[NN];
__device__ int g_esrc[ET];

__device__ __forceinline__ float lrelu(float a) { return a > 0.f ? a : NEG_SLOPE * a; }
__device__ __forceinline__ float to_tf32(float x) {
    unsigned u;
    asm("cvt.rna.tf32.f32 %0, %1;" : "=r"(u) : "f"(x));
    return __uint_as_float(u);
}

// bf16x2 accumulate macros: constant indices only, no address-of-register
#define ACC8(RV, EV) do {                                                            \
    float2 _f0 = __bfloat1622float2(*reinterpret_cast<const __nv_bfloat162*>(&(RV).x)); \
    float2 _f1 = __bfloat1622float2(*reinterpret_cast<const __nv_bfloat162*>(&(RV).y)); \
    float2 _f2 = __bfloat1622float2(*reinterpret_cast<const __nv_bfloat162*>(&(RV).z)); \
    float2 _f3 = __bfloat1622float2(*reinterpret_cast<const __nv_bfloat162*>(&(RV).w)); \
    acc[0] += (EV) * _f0.x; acc[1] += (EV) * _f0.y;                                  \
    acc[2] += (EV) * _f1.x; acc[3] += (EV) * _f1.y;                                  \
    acc[4] += (EV) * _f2.x; acc[5] += (EV) * _f2.y;                                  \
    acc[6] += (EV) * _f3.x; acc[7] += (EV) * _f3.y;                                  \
} while (0)

#define ACC4(RV, EV) do {                                                            \
    float2 _f0 = __bfloat1622float2(*reinterpret_cast<const __nv_bfloat162*>(&(RV).x)); \
    float2 _f1 = __bfloat1622float2(*reinterpret_cast<const __nv_bfloat162*>(&(RV).y)); \
    acc[0] += (EV) * _f0.x; acc[1] += (EV) * _f0.y;                                  \
    acc[2] += (EV) * _f1.x; acc[3] += (EV) * _f1.y;                                  \
} while (0)

// ---------------- init: zero histogram + pool + cnt ----------------
__global__ void init_kernel(float* __restrict__ pool) {
    int i = blockIdx.x * blockDim.x + threadIdx.x;
    if (i < NN)      g_hist[i] = 0;
    if (i < NG * C2) pool[i] = 0.f;
    if (i < NG)      g_cnt[i] = 0.f;
}

// ---------------- CSR build: histogram of dst ----------------
__global__ void hist_kernel(const int* __restrict__ ei) {
    int e = blockIdx.x * blockDim.x + threadIdx.x;
    if (e >= ET) return;
    int dn = (e < NE) ? ei[NE + e] : (e - NE);
    atomicAdd(&g_hist[dn], 1);
}

// ---------------- CSR build: exclusive scan, thread-serial chunks + warp-shuffle block scan ----------------
__global__ void scan_kernel() {   // launch with 1024 threads, 1 block
    __shared__ int warp_sums[32];
    const int t = threadIdx.x;
    const int PER = (NN + 1023) / 1024;   // 49
    const int base = t * PER;

    int sum = 0;
    for (int j = 0; j < PER; j++) {
        int idx = base + j;
        if (idx < NN) sum += g_hist[idx];
    }
    const int lane = t & 31, wid = t >> 5;
    int v = sum;
#pragma unroll
    for (int d = 1; d < 32; d <<= 1) {
        int x = __shfl_up_sync(0xffffffffu, v, d);
        if (lane >= d) v += x;
    }
    if (lane == 31) warp_sums[wid] = v;
    __syncthreads();
    if (wid == 0) {
        int w = warp_sums[lane];
#pragma unroll
        for (int d = 1; d < 32; d <<= 1) {
            int x = __shfl_up_sync(0xffffffffu, w, d);
            if (lane >= d) w += x;
        }
        warp_sums[lane] = w;
    }
    __syncthreads();
    int running = (v - sum) + (wid > 0 ? warp_sums[wid - 1] : 0);
    for (int j = 0; j < PER; j++) {
        int idx = base + j;
        if (idx < NN) {
            g_indptr[idx] = running;
            g_off[idx]    = running;
            running += g_hist[idx];
        }
    }
    if (t == 1023) g_indptr[NN] = running;
}

// ---------------- CSR build: scatter src ids grouped by dst ----------------
__global__ void scatter_kernel(const int* __restrict__ ei) {
    int e = blockIdx.x * blockDim.x + threadIdx.x;
    if (e >= ET) return;
    int s, dn;
    if (e < NE) { s = ei[e]; dn = ei[NE + e]; }
    else        { s = dn = e - NE; }
    int pos = atomicAdd(&g_off[dn], 1);
    g_esrc[pos] = s;
}

// ---------------- TF32 tensor-core GEMM: C[M,N] = A[M,K] @ B[K,N], row-major fp32 ----------------
// Also writes bf16 copy Cb straight from registers.
__global__ __launch_bounds__(256) void gemm_tf32_kernel(
    const float* __restrict__ A, const float* __restrict__ B,
    float* __restrict__ C, __nv_bfloat16* __restrict__ Cb,
    int M, int N, int K)
{
    __shared__ __align__(16) float As[2][128][20];  // [buf][m][k]
    __shared__ __align__(16) float Bs[2][128][20];  // [buf][n][k]

    const int t    = threadIdx.x;
    const int lane = t & 31;
    const int wid  = t >> 5;
    const int g    = lane >> 2;
    const int tig  = lane & 3;
    const int wm   = (wid >> 2) * 64;
    const int wn   = (wid & 3) * 32;
    const int bm   = blockIdx.y * 128;
    const int bn   = blockIdx.x * 128;

    const int ar = t >> 2;
    const int ac = (t & 3) * 4;
    const int brr = t >> 4;
    const int bcc = (t & 15) * 8;

    float acc[4][4][4];
#pragma unroll
    for (int i = 0; i < 4; i++)
#pragma unroll
        for (int j = 0; j < 4; j++)
#pragma unroll
            for (int r = 0; r < 4; r++) acc[i][j][r] = 0.f;

    const int NT = K / 16;
    float4 pa0, pa1, pb0, pb1;

    {
        pa0 = make_float4(0.f, 0.f, 0.f, 0.f); pa1 = pa0;
        if (bm + ar < M)      pa0 = *(const float4*)(A + (size_t)(bm + ar) * K + ac);
        if (bm + ar + 64 < M) pa1 = *(const float4*)(A + (size_t)(bm + ar + 64) * K + ac);
        pb0 = *(const float4*)(B + (size_t)brr * N + bn + bcc);
        pb1 = *(const float4*)(B + (size_t)brr * N + bn + bcc + 4);
        *(float4*)&As[0][ar][ac]      = make_float4(to_tf32(pa0.x), to_tf32(pa0.y), to_tf32(pa0.z), to_tf32(pa0.w));
        *(float4*)&As[0][ar + 64][ac] = make_float4(to_tf32(pa1.x), to_tf32(pa1.y), to_tf32(pa1.z), to_tf32(pa1.w));
        Bs[0][bcc + 0][brr] = to_tf32(pb0.x); Bs[0][bcc + 1][brr] = to_tf32(pb0.y);
        Bs[0][bcc + 2][brr] = to_tf32(pb0.z); Bs[0][bcc + 3][brr] = to_tf32(pb0.w);
        Bs[0][bcc + 4][brr] = to_tf32(pb1.x); Bs[0][bcc + 5][brr] = to_tf32(pb1.y);
        Bs[0][bcc + 6][brr] = to_tf32(pb1.z); Bs[0][bcc + 7][brr] = to_tf32(pb1.w);
    }
    __syncthreads();

    int buf = 0;
    for (int it = 0; it < NT; it++) {
        if (it + 1 < NT) {
            int k0 = (it + 1) * 16;
            pa0 = make_float4(0.f, 0.f, 0.f, 0.f); pa1 = pa0;
            if (bm + ar < M)      pa0 = *(const float4*)(A + (size_t)(bm + ar) * K + k0 + ac);
            if (bm + ar + 64 < M) pa1 = *(const float4*)(A + (size_t)(bm + ar + 64) * K + k0 + ac);
            pb0 = *(const float4*)(B + (size_t)(k0 + brr) * N + bn + bcc);
            pb1 = *(const float4*)(B + (size_t)(k0 + brr) * N + bn + bcc + 4);
        }
#pragma unroll
        for (int ks = 0; ks < 2; ks++) {
            const int kk = ks * 8;
            unsigned af[4][4], bf[4][2];
#pragma unroll
            for (int i = 0; i < 4; i++) {
                int r = wm + i * 16 + g;
                af[i][0] = __float_as_uint(As[buf][r][kk + tig]);
                af[i][1] = __float_as_uint(As[buf][r + 8][kk + tig]);
                af[i][2] = __float_as_uint(As[buf][r][kk + tig + 4]);
                af[i][3] = __float_as_uint(As[buf][r + 8][kk + tig + 4]);
            }
#pragma unroll
            for (int j = 0; j < 4; j++) {
                int n = wn + j * 8 + g;
                bf[j][0] = __float_as_uint(Bs[buf][n][kk + tig]);
                bf[j][1] = __float_as_uint(Bs[buf][n][kk + tig + 4]);
            }
#pragma unroll
            for (int i = 0; i < 4; i++)
#pragma unroll
                for (int j = 0; j < 4; j++) {
                    asm volatile(
                        "mma.sync.aligned.m16n8k8.row.col.f32.tf32.tf32.f32 "
                        "{%0,%1,%2,%3}, {%4,%5,%6,%7}, {%8,%9}, {%0,%1,%2,%3};"
                        : "+f"(acc[i][j][0]), "+f"(acc[i][j][1]),
                          "+f"(acc[i][j][2]), "+f"(acc[i][j][3])
                        : "r"(af[i][0]), "r"(af[i][1]), "r"(af[i][2]), "r"(af[i][3]),
                          "r"(bf[j][0]), "r"(bf[j][1]));
                }
        }
        if (it + 1 < NT) {
            int nb = buf ^ 1;
            *(float4*)&As[nb][ar][ac]      = make_float4(to_tf32(pa0.x), to_tf32(pa0.y), to_tf32(pa0.z), to_tf32(pa0.w));
            *(float4*)&As[nb][ar + 64][ac] = make_float4(to_tf32(pa1.x), to_tf32(pa1.y), to_tf32(pa1.z), to_tf32(pa1.w));
            Bs[nb][bcc + 0][brr] = to_tf32(pb0.x); Bs[nb][bcc + 1][brr] = to_tf32(pb0.y);
            Bs[nb][bcc + 2][brr] = to_tf32(pb0.z); Bs[nb][bcc + 3][brr] = to_tf32(pb0.w);
            Bs[nb][bcc + 4][brr] = to_tf32(pb1.x); Bs[nb][bcc + 5][brr] = to_tf32(pb1.y);
            Bs[nb][bcc + 6][brr] = to_tf32(pb1.z); Bs[nb][bcc + 7][brr] = to_tf32(pb1.w);
        }
        __syncthreads();
        buf ^= 1;
    }

#pragma unroll
    for (int i = 0; i < 4; i++) {
#pragma unroll
        for (int j = 0; j < 4; j++) {
            int row = bm + wm + i * 16 + g;
            int col = bn + wn + j * 8 + 2 * tig;
            if (row < M) {
                *(float2*)(C + (size_t)row * N + col) = make_float2(acc[i][j][0], acc[i][j][1]);
                __nv_bfloat162 bb = __floats2bfloat162_rn(acc[i][j][0], acc[i][j][1]);
                *(unsigned*)(Cb + (size_t)row * N + col) = *reinterpret_cast<unsigned*>(&bb);
            }
            if (row + 8 < M) {
                *(float2*)(C + (size_t)(row + 8) * N + col) = make_float2(acc[i][j][2], acc[i][j][3]);
                __nv_bfloat162 bb = __floats2bfloat162_rn(acc[i][j][2], acc[i][j][3]);
                *(unsigned*)(Cb + (size_t)(row + 8) * N + col) = *reinterpret_cast<unsigned*>(&bb);
            }
        }
    }
}

// ---------------- attention scores ----------------
__global__ void attn_scores_kernel(const float* __restrict__ h,
                                   const float* __restrict__ att_s,
                                   const float* __restrict__ att_d,
                                   float* __restrict__ asrc, float* __restrict__ adst,
                                   int heads, int ch)
{
    int i = blockIdx.x * blockDim.x + threadIdx.x;
    if (i >= NN * heads) return;
    int node = i / heads, hd = i - node * heads;
    const float4* hp = (const float4*)(h + (size_t)node * heads * ch + hd * ch);
    const float4* sp = (const float4*)(att_s + hd * ch);
    const float4* dp = (const float4*)(att_d + hd * ch);
    float s = 0.f, d = 0.f;
    for (int c = 0; c < ch / 4; c++) {
        float4 v = hp[c], a = sp[c], b = dp[c];
        s += v.x * a.x + v.y * a.y + v.z * a.z + v.w * a.w;
        d += v.x * b.x + v.y * b.y + v.z * b.z + v.w * b.w;
    }
    asrc[i] = s; adst[i] = d;
}

// ---------------- CSR aggregation: one warp per dst node, clean 4-wide unroll ----------------
template <int H, int C, bool POOL>
__global__ __launch_bounds__(256) void agg_kernel(
    const __nv_bfloat16* __restrict__ hb,
    const float* __restrict__ asrc, const float* __restrict__ adst,
    const float* __restrict__ bias,
    const int* __restrict__ batch,
    float* __restrict__ outp)
{
    int n = (blockIdx.x * blockDim.x + threadIdx.x) >> 5;
    int lane = threadIdx.x & 31;
    if (n >= NN) return;

    constexpr int CPL = C / 32;          // 8 (C=256) or 4 (C=128)
    const int hd = (lane * CPL) / (C / H);

    const float adn = adst[n * H + hd];
    const int beg = g_indptr[n];
    const int end = g_indptr[n + 1];

    float acc[CPL];
#pragma unroll
    for (int j = 0; j < CPL; j++) acc[j] = 0.f;
    float den = 0.f;

    const int laneoff = lane * CPL;
    int i = beg;

    if (CPL == 8) {
        for (; i + 3 < end; i += 4) {
            int s0 = g_esrc[i], s1 = g_esrc[i + 1], s2 = g_esrc[i + 2], s3 = g_esrc[i + 3];
            float a0 = asrc[s0 * H + hd], a1 = asrc[s1 * H + hd];
            float a2 = asrc[s2 * H + hd], a3 = asrc[s3 * H + hd];
            uint4 r0 = *(const uint4*)(hb + (size_t)s0 * C + laneoff);
            uint4 r1 = *(const uint4*)(hb + (size_t)s1 * C + laneoff);
            uint4 r2 = *(const uint4*)(hb + (size_t)s2 * C + laneoff);
            uint4 r3 = *(const uint4*)(hb + (size_t)s3 * C + laneoff);
            float e0 = __expf(lrelu(a0 + adn)), e1 = __expf(lrelu(a1 + adn));
            float e2 = __expf(lrelu(a2 + adn)), e3 = __expf(lrelu(a3 + adn));
            den += (e0 + e1) + (e2 + e3);
            ACC8(r0, e0); ACC8(r1, e1); ACC8(r2, e2); ACC8(r3, e3);
        }
        for (; i < end; i++) {
            int s = g_esrc[i];
            float a = asrc[s * H + hd];
            uint4 r = *(const uint4*)(hb + (size_t)s * C + laneoff);
            float e = __expf(lrelu(a + adn));
            den += e;
            ACC8(r, e);
        }
    } else {
        for (; i + 3 < end; i += 4) {
            int s0 = g_esrc[i], s1 = g_esrc[i + 1], s2 = g_esrc[i + 2], s3 = g_esrc[i + 3];
            float a0 = asrc[s0 * H + hd], a1 = asrc[s1 * H + hd];
            float a2 = asrc[s2 * H + hd], a3 = asrc[s3 * H + hd];
            uint2 r0 = *(const uint2*)(hb + (size_t)s0 * C + laneoff);
            uint2 r1 = *(const uint2*)(hb + (size_t)s1 * C + laneoff);
            uint2 r2 = *(const uint2*)(hb + (size_t)s2 * C + laneoff);
            uint2 r3 = *(const uint2*)(hb + (size_t)s3 * C + laneoff);
            float e0 = __expf(lrelu(a0 + adn)), e1 = __expf(lrelu(a1 + adn));
            float e2 = __expf(lrelu(a2 + adn)), e3 = __expf(lrelu(a3 + adn));
            den += (e0 + e1) + (e2 + e3);
            ACC4(r0, e0); ACC4(r1, e1); ACC4(r2, e2); ACC4(r3, e3);
        }
        for (; i < end; i++) {
            int s = g_esrc[i];
            float a = asrc[s * H + hd];
            uint2 r = *(const uint2*)(hb + (size_t)s * C + laneoff);
            float e = __expf(lrelu(a + adn));
            den += e;
            ACC4(r, e);
        }
    }

    const float inv = 1.f / (den + EPSV);
    if (POOL) {
        int g = batch[n];
        float* pp = outp + (size_t)g * C + laneoff;
#pragma unroll
        for (int j = 0; j < CPL; j++) {
            float v = acc[j] * inv + bias[laneoff + j];
            v = v > 0.f ? v : 0.f;
            atomicAdd(pp + j, v);
        }
    } else {
        float* op = outp + (size_t)n * C + laneoff;
#pragma unroll
        for (int j = 0; j < CPL; j++) {
            float v = acc[j] * inv + bias[laneoff + j];
            acc[j] = v > 0.f ? v : 0.f;
        }
#pragma unroll
        for (int j = 0; j < CPL; j += 4)
            *(float4*)(op + j) = make_float4(acc[j], acc[j + 1], acc[j + 2], acc[j + 3]);
    }
}

// ---------------- node count per graph ----------------
__global__ void cnt_kernel(const int* __restrict__ batch) {
    int n = blockIdx.x * blockDim.x + threadIdx.x;
    if (n >= NN) return;
    atomicAdd(&g_cnt[batch[n]], 1.0f);
}

__global__ void pool_div_kernel(float* __restrict__ pool) {
    int i = blockIdx.x * blockDim.x + threadIdx.x;
    if (i >= NG * C2) return;
    int g = i >> 7;
    float c = g_cnt[g];
    pool[i] = pool[i] / (c > 1.f ? c : 1.f);
}

// ---------------- host launcher (graph-capturable, default stream) ----------------
extern "C" void kernel_launch(void* const* d_in, const int* in_sizes, int n_in,
                              void* d_out, int out_size)
{
    const float* x    = (const float*)d_in[0];
    const float* W1   = (const float*)d_in[1];
    const float* as1  = (const float*)d_in[2];
    const float* ad1  = (const float*)d_in[3];
    const float* b1   = (const float*)d_in[4];
    const float* W2   = (const float*)d_in[5];
    const float* as2  = (const float*)d_in[6];
    const float* ad2  = (const float*)d_in[7];
    const float* b2   = (const float*)d_in[8];
    const int*   ei   = (const int*)d_in[9];
    const int*   batch= (const int*)d_in[10];
    float* pool = (float*)d_out;

    float *p_h1, *p_out1, *p_h2;
    float *p_asrc1, *p_adst1, *p_asrc2, *p_adst2;
    __nv_bfloat16 *p_hb1, *p_hb2;
    cudaGetSymbolAddress((void**)&p_h1, g_h1);
    cudaGetSymbolAddress((void**)&p_out1, g_out1);
    cudaGetSymbolAddress((void**)&p_h2, g_h2);
    cudaGetSymbolAddress((void**)&p_hb1, g_hb1);
    cudaGetSymbolAddress((void**)&p_hb2, g_hb2);
    cudaGetSymbolAddress((void**)&p_asrc1, g_asrc1);
    cudaGetSymbolAddress((void**)&p_adst1, g_adst1);
    cudaGetSymbolAddress((void**)&p_asrc2, g_asrc2);
    cudaGetSymbolAddress((void**)&p_adst2, g_adst2);

    const int TB = 256;

    // 1) init (hist/pool/cnt)
    init_kernel<<<(NN + TB - 1) / TB, TB>>>(pool);
    // 2) histogram
    hist_kernel<<<(ET + TB - 1) / TB, TB>>>(ei);
    // 3) scan
    scan_kernel<<<1, 1024>>>();
    // 4) gemm1 (placed 4th so the profiler's fixed capture slot lands on it)
    {
        dim3 grid(C1 / 128, (NN + 127) / 128);
        gemm_tf32_kernel<<<grid, 256>>>(x, W1, p_h1, p_hb1, NN, C1, 256);
    }
    // 5) scatter (completes CSR; needed before agg1)
    scatter_kernel<<<(ET + TB - 1) / TB, TB>>>(ei);
    // 6) attention scores layer 1
    attn_scores_kernel<<<(NN * H1 + TB - 1) / TB, TB>>>(p_h1, as1, ad1, p_asrc1, p_adst1, H1, CH1);
    // 7) CSR aggregation layer 1 -> g_out1
    agg_kernel<H1, C1, false><<<(NN * 32 + TB - 1) / TB, TB>>>(
        p_hb1, p_asrc1, p_adst1, b1, batch, p_out1);
    // 8) gemm2
    {
        dim3 grid(C2 / 128, (NN + 127) / 128);
        gemm_tf32_kernel<<<grid, 256>>>(p_out1, W2, p_h2, p_hb2, NN, C2, 256);
    }
    // 9) attention scores layer 2
    attn_scores_kernel<<<(NN + TB - 1) / TB, TB>>>(p_h2, as2, ad2, p_asrc2, p_adst2, 1, C2);
    // 10) graph node counts
    cnt_kernel<<<(NN + TB - 1) / TB, TB>>>(batch);
    // 11) CSR aggregation layer 2 -> pool
    agg_kernel<1, C2, true><<<(NN * 32 + TB - 1) / TB, TB>>>(
        p_hb2, p_asrc2, p_adst2, b2, batch, pool);
    // 12) mean
    pool_div_kernel<<<(NG * C2 + TB - 1) / TB, TB>>>(pool);
}

// round 16
// speedup vs baseline: 2.7931x; 1.1400x over previous
#include <cuda_runtime.h>
#include <cuda_bf16.h>
#include <cstdint>

#define NN 50000
#define NE 800000
#define ET 850000   // NE + NN self loops
#define NG 100
#define C1 256      // heads*hid = 4*64
#define H1 4
#define CH1 64
#define C2 128
#define NEG_SLOPE 0.2f
#define EPSV 1e-16f

// ---------------- scratch (device globals; no allocation allowed) ----------------
__device__ __align__(16) float g_h1[NN * C1];      // x @ W1 (fp32)
__device__ __align__(16) float g_out1[NN * C1];    // layer-1 final (fp32, GEMM2 input)
__device__ __align__(16) float g_h2[NN * C2];      // relu_out1 @ W2 (fp32)
__device__ __align__(16) __nv_bfloat16 g_hb1[NN * C1];  // bf16 copy of h1 for gather
__device__ __align__(16) __nv_bfloat16 g_hb2[NN * C2];  // bf16 copy of h2 for gather
__device__ __align__(16) float g_asrc1[NN * H1];
__device__ __align__(16) float g_adst1[NN * H1];
__device__ float g_asrc2[NN], g_adst2[NN];
__device__ float g_cnt[NG];
// CSR scratch
__device__ int g_hist[NN];
__device__ int g_indptr[NN + 1];
__device__ int g_off[NN];
__device__ int g_esrc[ET];

__device__ __forceinline__ float lrelu(float a) { return a > 0.f ? a : NEG_SLOPE * a; }
__device__ __forceinline__ float to_tf32(float x) {
    unsigned u;
    asm("cvt.rna.tf32.f32 %0, %1;" : "=r"(u) : "f"(x));
    return __uint_as_float(u);
}

// bf16x2 accumulate macros: constant indices only, no address-of-register
#define ACC8(RV, EV) do {                                                            \
    float2 _f0 = __bfloat1622float2(*reinterpret_cast<const __nv_bfloat162*>(&(RV).x)); \
    float2 _f1 = __bfloat1622float2(*reinterpret_cast<const __nv_bfloat162*>(&(RV).y)); \
    float2 _f2 = __bfloat1622float2(*reinterpret_cast<const __nv_bfloat162*>(&(RV).z)); \
    float2 _f3 = __bfloat1622float2(*reinterpret_cast<const __nv_bfloat162*>(&(RV).w)); \
    acc[0] += (EV) * _f0.x; acc[1] += (EV) * _f0.y;                                  \
    acc[2] += (EV) * _f1.x; acc[3] += (EV) * _f1.y;                                  \
    acc[4] += (EV) * _f2.x; acc[5] += (EV) * _f2.y;                                  \
    acc[6] += (EV) * _f3.x; acc[7] += (EV) * _f3.y;                                  \
} while (0)

#define ACC4(RV, EV) do {                                                            \
    float2 _f0 = __bfloat1622float2(*reinterpret_cast<const __nv_bfloat162*>(&(RV).x)); \
    float2 _f1 = __bfloat1622float2(*reinterpret_cast<const __nv_bfloat162*>(&(RV).y)); \
    acc[0] += (EV) * _f0.x; acc[1] += (EV) * _f0.y;                                  \
    acc[2] += (EV) * _f1.x; acc[3] += (EV) * _f1.y;                                  \
} while (0)

// ---------------- init: zero histogram + pool + cnt ----------------
__global__ void init_kernel(float* __restrict__ pool) {
    int i = blockIdx.x * blockDim.x + threadIdx.x;
    if (i < NN)      g_hist[i] = 0;
    if (i < NG * C2) pool[i] = 0.f;
    if (i < NG)      g_cnt[i] = 0.f;
}

// ---------------- CSR build: histogram of dst ----------------
__global__ void hist_kernel(const int* __restrict__ ei) {
    int e = blockIdx.x * blockDim.x + threadIdx.x;
    if (e >= ET) return;
    int dn = (e < NE) ? ei[NE + e] : (e - NE);
    atomicAdd(&g_hist[dn], 1);
}

// ---------------- CSR build: exclusive scan, thread-serial chunks + warp-shuffle block scan ----------------
__global__ void scan_kernel() {   // launch with 1024 threads, 1 block
    __shared__ int warp_sums[32];
    const int t = threadIdx.x;
    const int PER = (NN + 1023) / 1024;   // 49
    const int base = t * PER;

    int sum = 0;
    for (int j = 0; j < PER; j++) {
        int idx = base + j;
        if (idx < NN) sum += g_hist[idx];
    }
    const int lane = t & 31, wid = t >> 5;
    int v = sum;
#pragma unroll
    for (int d = 1; d < 32; d <<= 1) {
        int x = __shfl_up_sync(0xffffffffu, v, d);
        if (lane >= d) v += x;
    }
    if (lane == 31) warp_sums[wid] = v;
    __syncthreads();
    if (wid == 0) {
        int w = warp_sums[lane];
#pragma unroll
        for (int d = 1; d < 32; d <<= 1) {
            int x = __shfl_up_sync(0xffffffffu, w, d);
            if (lane >= d) w += x;
        }
        warp_sums[lane] = w;
    }
    __syncthreads();
    int running = (v - sum) + (wid > 0 ? warp_sums[wid - 1] : 0);
    for (int j = 0; j < PER; j++) {
        int idx = base + j;
        if (idx < NN) {
            g_indptr[idx] = running;
            g_off[idx]    = running;
            running += g_hist[idx];
        }
    }
    if (t == 1023) g_indptr[NN] = running;
}

// ---------------- CSR build: scatter src ids grouped by dst ----------------
__global__ void scatter_kernel(const int* __restrict__ ei) {
    int e = blockIdx.x * blockDim.x + threadIdx.x;
    if (e >= ET) return;
    int s, dn;
    if (e < NE) { s = ei[e]; dn = ei[NE + e]; }
    else        { s = dn = e - NE; }
    int pos = atomicAdd(&g_off[dn], 1);
    g_esrc[pos] = s;
}

// ---------------- TF32 tensor-core GEMM: C[M,N] = A[M,K] @ B[K,N], row-major fp32 ----------------
// Also writes bf16 copy Cb straight from registers.
// A smem [m][k] stride 20; B smem [k][n] stride 136 (NO transpose -> no 16-way store conflict).
// Fragment banks: A (20m+k)%32 and B (8k+n)%32 are both 32-permutations -> conflict-free.
__global__ __launch_bounds__(256) void gemm_tf32_kernel(
    const float* __restrict__ A, const float* __restrict__ B,
    float* __restrict__ C, __nv_bfloat16* __restrict__ Cb,
    int M, int N, int K)
{
    __shared__ __align__(16) float As[2][128][20];   // [buf][m][k]
    __shared__ __align__(16) float Bs[2][16][136];   // [buf][k][n]

    const int t    = threadIdx.x;
    const int lane = t & 31;
    const int wid  = t >> 5;
    const int g    = lane >> 2;   // 0..7
    const int tig  = lane & 3;    // 0..3
    const int wm   = (wid >> 2) * 64;
    const int wn   = (wid & 3) * 32;
    const int bm   = blockIdx.y * 128;
    const int bn   = blockIdx.x * 128;

    const int ar = t >> 2;            // 0..63 (+64)
    const int ac = (t & 3) * 4;
    const int bkr = t >> 4;           // 0..15 (k row)
    const int bnc = (t & 15) * 8;     // n col group

    float acc[4][4][4];
#pragma unroll
    for (int i = 0; i < 4; i++)
#pragma unroll
        for (int j = 0; j < 4; j++)
#pragma unroll
            for (int r = 0; r < 4; r++) acc[i][j][r] = 0.f;

    const int NT = K / 16;
    float4 pa0, pa1, pb0, pb1;

    {
        pa0 = make_float4(0.f, 0.f, 0.f, 0.f); pa1 = pa0;
        if (bm + ar < M)      pa0 = *(const float4*)(A + (size_t)(bm + ar) * K + ac);
        if (bm + ar + 64 < M) pa1 = *(const float4*)(A + (size_t)(bm + ar + 64) * K + ac);
        pb0 = *(const float4*)(B + (size_t)bkr * N + bn + bnc);
        pb1 = *(const float4*)(B + (size_t)bkr * N + bn + bnc + 4);
        *(float4*)&As[0][ar][ac]      = make_float4(to_tf32(pa0.x), to_tf32(pa0.y), to_tf32(pa0.z), to_tf32(pa0.w));
        *(float4*)&As[0][ar + 64][ac] = make_float4(to_tf32(pa1.x), to_tf32(pa1.y), to_tf32(pa1.z), to_tf32(pa1.w));
        *(float4*)&Bs[0][bkr][bnc]     = make_float4(to_tf32(pb0.x), to_tf32(pb0.y), to_tf32(pb0.z), to_tf32(pb0.w));
        *(float4*)&Bs[0][bkr][bnc + 4] = make_float4(to_tf32(pb1.x), to_tf32(pb1.y), to_tf32(pb1.z), to_tf32(pb1.w));
    }
    __syncthreads();

    int buf = 0;
    for (int it = 0; it < NT; it++) {
        if (it + 1 < NT) {
            int k0 = (it + 1) * 16;
            pa0 = make_float4(0.f, 0.f, 0.f, 0.f); pa1 = pa0;
            if (bm + ar < M)      pa0 = *(const float4*)(A + (size_t)(bm + ar) * K + k0 + ac);
            if (bm + ar + 64 < M) pa1 = *(const float4*)(A + (size_t)(bm + ar + 64) * K + k0 + ac);
            pb0 = *(const float4*)(B + (size_t)(k0 + bkr) * N + bn + bnc);
            pb1 = *(const float4*)(B + (size_t)(k0 + bkr) * N + bn + bnc + 4);
        }
#pragma unroll
        for (int ks = 0; ks < 2; ks++) {
            const int kk = ks * 8;
            unsigned af[4][4], bf[4][2];
#pragma unroll
            for (int i = 0; i < 4; i++) {
                int r = wm + i * 16 + g;
                af[i][0] = __float_as_uint(As[buf][r][kk + tig]);
                af[i][1] = __float_as_uint(As[buf][r + 8][kk + tig]);
                af[i][2] = __float_as_uint(As[buf][r][kk + tig + 4]);
                af[i][3] = __float_as_uint(As[buf][r + 8][kk + tig + 4]);
            }
#pragma unroll
            for (int j = 0; j < 4; j++) {
                int n = wn + j * 8 + g;
                bf[j][0] = __float_as_uint(Bs[buf][kk + tig][n]);
                bf[j][1] = __float_as_uint(Bs[buf][kk + tig + 4][n]);
            }
#pragma unroll
            for (int i = 0; i < 4; i++)
#pragma unroll
                for (int j = 0; j < 4; j++) {
                    asm volatile(
                        "mma.sync.aligned.m16n8k8.row.col.f32.tf32.tf32.f32 "
                        "{%0,%1,%2,%3}, {%4,%5,%6,%7}, {%8,%9}, {%0,%1,%2,%3};"
                        : "+f"(acc[i][j][0]), "+f"(acc[i][j][1]),
                          "+f"(acc[i][j][2]), "+f"(acc[i][j][3])
                        : "r"(af[i][0]), "r"(af[i][1]), "r"(af[i][2]), "r"(af[i][3]),
                          "r"(bf[j][0]), "r"(bf[j][1]));
                }
        }
        if (it + 1 < NT) {
            int nb = buf ^ 1;
            *(float4*)&As[nb][ar][ac]      = make_float4(to_tf32(pa0.x), to_tf32(pa0.y), to_tf32(pa0.z), to_tf32(pa0.w));
            *(float4*)&As[nb][ar + 64][ac] = make_float4(to_tf32(pa1.x), to_tf32(pa1.y), to_tf32(pa1.z), to_tf32(pa1.w));
            *(float4*)&Bs[nb][bkr][bnc]     = make_float4(to_tf32(pb0.x), to_tf32(pb0.y), to_tf32(pb0.z), to_tf32(pb0.w));
            *(float4*)&Bs[nb][bkr][bnc + 4] = make_float4(to_tf32(pb1.x), to_tf32(pb1.y), to_tf32(pb1.z), to_tf32(pb1.w));
        }
        __syncthreads();
        buf ^= 1;
    }

#pragma unroll
    for (int i = 0; i < 4; i++) {
#pragma unroll
        for (int j = 0; j < 4; j++) {
            int row = bm + wm + i * 16 + g;
            int col = bn + wn + j * 8 + 2 * tig;
            if (row < M) {
                *(float2*)(C + (size_t)row * N + col) = make_float2(acc[i][j][0], acc[i][j][1]);
                __nv_bfloat162 bb = __floats2bfloat162_rn(acc[i][j][0], acc[i][j][1]);
                *(unsigned*)(Cb + (size_t)row * N + col) = *reinterpret_cast<unsigned*>(&bb);
            }
            if (row + 8 < M) {
                *(float2*)(C + (size_t)(row + 8) * N + col) = make_float2(acc[i][j][2], acc[i][j][3]);
                __nv_bfloat162 bb = __floats2bfloat162_rn(acc[i][j][2], acc[i][j][3]);
                *(unsigned*)(Cb + (size_t)(row + 8) * N + col) = *reinterpret_cast<unsigned*>(&bb);
            }
        }
    }
}

// ---------------- attention scores ----------------
__global__ void attn_scores_kernel(const float* __restrict__ h,
                                   const float* __restrict__ att_s,
                                   const float* __restrict__ att_d,
                                   float* __restrict__ asrc, float* __restrict__ adst,
                                   int heads, int ch)
{
    int i = blockIdx.x * blockDim.x + threadIdx.x;
    if (i >= NN * heads) return;
    int node = i / heads, hd = i - node * heads;
    const float4* hp = (const float4*)(h + (size_t)node * heads * ch + hd * ch);
    const float4* sp = (const float4*)(att_s + hd * ch);
    const float4* dp = (const float4*)(att_d + hd * ch);
    float s = 0.f, d = 0.f;
    for (int c = 0; c < ch / 4; c++) {
        float4 v = hp[c], a = sp[c], b = dp[c];
        s += v.x * a.x + v.y * a.y + v.z * a.z + v.w * a.w;
        d += v.x * b.x + v.y * b.y + v.z * b.z + v.w * b.w;
    }
    asrc[i] = s; adst[i] = d;
}

// ---------------- CSR aggregation: one warp per dst node, clean 4-wide unroll ----------------
template <int H, int C, bool POOL>
__global__ __launch_bounds__(256) void agg_kernel(
    const __nv_bfloat16* __restrict__ hb,
    const float* __restrict__ asrc, const float* __restrict__ adst,
    const float* __restrict__ bias,
    const int* __restrict__ batch,
    float* __restrict__ outp)
{
    int n = (blockIdx.x * blockDim.x + threadIdx.x) >> 5;
    int lane = threadIdx.x & 31;
    if (n >= NN) return;

    constexpr int CPL = C / 32;          // 8 (C=256) or 4 (C=128)
    const int hd = (lane * CPL) / (C / H);

    const float adn = adst[n * H + hd];
    const int beg = g_indptr[n];
    const int end = g_indptr[n + 1];

    float acc[CPL];
#pragma unroll
    for (int j = 0; j < CPL; j++) acc[j] = 0.f;
    float den = 0.f;

    const int laneoff = lane * CPL;
    int i = beg;

    if (CPL == 8) {
        for (; i + 3 < end; i += 4) {
            int s0 = g_esrc[i], s1 = g_esrc[i + 1], s2 = g_esrc[i + 2], s3 = g_esrc[i + 3];
            float a0 = asrc[s0 * H + hd], a1 = asrc[s1 * H + hd];
            float a2 = asrc[s2 * H + hd], a3 = asrc[s3 * H + hd];
            uint4 r0 = *(const uint4*)(hb + (size_t)s0 * C + laneoff);
            uint4 r1 = *(const uint4*)(hb + (size_t)s1 * C + laneoff);
            uint4 r2 = *(const uint4*)(hb + (size_t)s2 * C + laneoff);
            uint4 r3 = *(const uint4*)(hb + (size_t)s3 * C + laneoff);
            float e0 = __expf(lrelu(a0 + adn)), e1 = __expf(lrelu(a1 + adn));
            float e2 = __expf(lrelu(a2 + adn)), e3 = __expf(lrelu(a3 + adn));
            den += (e0 + e1) + (e2 + e3);
            ACC8(r0, e0); ACC8(r1, e1); ACC8(r2, e2); ACC8(r3, e3);
        }
        for (; i < end; i++) {
            int s = g_esrc[i];
            float a = asrc[s * H + hd];
            uint4 r = *(const uint4*)(hb + (size_t)s * C + laneoff);
            float e = __expf(lrelu(a + adn));
            den += e;
            ACC8(r, e);
        }
    } else {
        for (; i + 3 < end; i += 4) {
            int s0 = g_esrc[i], s1 = g_esrc[i + 1], s2 = g_esrc[i + 2], s3 = g_esrc[i + 3];
            float a0 = asrc[s0 * H + hd], a1 = asrc[s1 * H + hd];
            float a2 = asrc[s2 * H + hd], a3 = asrc[s3 * H + hd];
            uint2 r0 = *(const uint2*)(hb + (size_t)s0 * C + laneoff);
            uint2 r1 = *(const uint2*)(hb + (size_t)s1 * C + laneoff);
            uint2 r2 = *(const uint2*)(hb + (size_t)s2 * C + laneoff);
            uint2 r3 = *(const uint2*)(hb + (size_t)s3 * C + laneoff);
            float e0 = __expf(lrelu(a0 + adn)), e1 = __expf(lrelu(a1 + adn));
            float e2 = __expf(lrelu(a2 + adn)), e3 = __expf(lrelu(a3 + adn));
            den += (e0 + e1) + (e2 + e3);
            ACC4(r0, e0); ACC4(r1, e1); ACC4(r2, e2); ACC4(r3, e3);
        }
        for (; i < end; i++) {
            int s = g_esrc[i];
            float a = asrc[s * H + hd];
            uint2 r = *(const uint2*)(hb + (size_t)s * C + laneoff);
            float e = __expf(lrelu(a + adn));
            den += e;
            ACC4(r, e);
        }
    }

    const float inv = 1.f / (den + EPSV);
    if (POOL) {
        int g = batch[n];
        float* pp = outp + (size_t)g * C + laneoff;
#pragma unroll
        for (int j = 0; j < CPL; j++) {
            float v = acc[j] * inv + bias[laneoff + j];
            v = v > 0.f ? v : 0.f;
            atomicAdd(pp + j, v);
        }
    } else {
        float* op = outp + (size_t)n * C + laneoff;
#pragma unroll
        for (int j = 0; j < CPL; j++) {
            float v = acc[j] * inv + bias[laneoff + j];
            acc[j] = v > 0.f ? v : 0.f;
        }
#pragma unroll
        for (int j = 0; j < CPL; j += 4)
            *(float4*)(op + j) = make_float4(acc[j], acc[j + 1], acc[j + 2], acc[j + 3]);
    }
}

// ---------------- node count per graph ----------------
__global__ void cnt_kernel(const int* __restrict__ batch) {
    int n = blockIdx.x * blockDim.x + threadIdx.x;
    if (n >= NN) return;
    atomicAdd(&g_cnt[batch[n]], 1.0f);
}

__global__ void pool_div_kernel(float* __restrict__ pool) {
    int i = blockIdx.x * blockDim.x + threadIdx.x;
    if (i >= NG * C2) return;
    int g = i >> 7;
    float c = g_cnt[g];
    pool[i] = pool[i] / (c > 1.f ? c : 1.f);
}

// ---------------- host launcher (graph-capturable, default stream) ----------------
extern "C" void kernel_launch(void* const* d_in, const int* in_sizes, int n_in,
                              void* d_out, int out_size)
{
    const float* x    = (const float*)d_in[0];
    const float* W1   = (const float*)d_in[1];
    const float* as1  = (const float*)d_in[2];
    const float* ad1  = (const float*)d_in[3];
    const float* b1   = (const float*)d_in[4];
    const float* W2   = (const float*)d_in[5];
    const float* as2  = (const float*)d_in[6];
    const float* ad2  = (const float*)d_in[7];
    const float* b2   = (const float*)d_in[8];
    const int*   ei   = (const int*)d_in[9];
    const int*   batch= (const int*)d_in[10];
    float* pool = (float*)d_out;

    float *p_h1, *p_out1, *p_h2;
    float *p_asrc1, *p_adst1, *p_asrc2, *p_adst2;
    __nv_bfloat16 *p_hb1, *p_hb2;
    cudaGetSymbolAddress((void**)&p_h1, g_h1);
    cudaGetSymbolAddress((void**)&p_out1, g_out1);
    cudaGetSymbolAddress((void**)&p_h2, g_h2);
    cudaGetSymbolAddress((void**)&p_hb1, g_hb1);
    cudaGetSymbolAddress((void**)&p_hb2, g_hb2);
    cudaGetSymbolAddress((void**)&p_asrc1, g_asrc1);
    cudaGetSymbolAddress((void**)&p_adst1, g_adst1);
    cudaGetSymbolAddress((void**)&p_asrc2, g_asrc2);
    cudaGetSymbolAddress((void**)&p_adst2, g_adst2);

    const int TB = 256;

    // 1) init (hist/pool/cnt)
    init_kernel<<<(NN + TB - 1) / TB, TB>>>(pool);
    // 2) histogram
    hist_kernel<<<(ET + TB - 1) / TB, TB>>>(ei);
    // 3) scan
    scan_kernel<<<1, 1024>>>();
    // 4) gemm1 (profiler slot 4 -> direct measurement of the fix)
    {
        dim3 grid(C1 / 128, (NN + 127) / 128);
        gemm_tf32_kernel<<<grid, 256>>>(x, W1, p_h1, p_hb1, NN, C1, 256);
    }
    // 5) scatter (completes CSR; needed before agg1)
    scatter_kernel<<<(ET + TB - 1) / TB, TB>>>(ei);
    // 6) attention scores layer 1
    attn_scores_kernel<<<(NN * H1 + TB - 1) / TB, TB>>>(p_h1, as1, ad1, p_asrc1, p_adst1, H1, CH1);
    // 7) CSR aggregation layer 1 -> g_out1
    agg_kernel<H1, C1, false><<<(NN * 32 + TB - 1) / TB, TB>>>(
        p_hb1, p_asrc1, p_adst1, b1, batch, p_out1);
    // 8) gemm2
    {
        dim3 grid(C2 / 128, (NN + 127) / 128);
        gemm_tf32_kernel<<<grid, 256>>>(p_out1, W2, p_h2, p_hb2, NN, C2, 256);
    }
    // 9) attention scores layer 2
    attn_scores_kernel<<<(NN + TB - 1) / TB, TB>>>(p_h2, as2, ad2, p_asrc2, p_adst2, 1, C2);
    // 10) graph node counts
    cnt_kernel<<<(NN + TB - 1) / TB, TB>>>(batch);
    // 11) CSR aggregation layer 2 -> pool
    agg_kernel<1, C2, true><<<(NN * 32 + TB - 1) / TB, TB>>>(
        p_hb2, p_asrc2, p_adst2, b2, batch, pool);
    // 12) mean
    pool_div_kernel<<<(NG * C2 + TB - 1) / TB, TB>>>(pool);
}

// round 17
// speedup vs baseline: 2.8219x; 1.0103x over previous
#include <cuda_runtime.h>
#include <cuda_bf16.h>
#include <cstdint>

#define NN 50000
#define NE 800000
#define ET 850000   // NE + NN self loops
#define NG 100
#define C1 256      // heads*hid = 4*64
#define H1 4
#define CH1 64
#define C2 128
#define NEG_SLOPE 0.2f
#define EPSV 1e-16f

// ---------------- scratch (device globals; no allocation allowed) ----------------
__device__ __align__(16) float g_h1[NN * C1];      // x @ W1 (fp32)
__device__ __align__(16) float g_out1[NN * C1];    // layer-1 final (fp32, GEMM2 input)
__device__ __align__(16) float g_h2[NN * C2];      // relu_out1 @ W2 (fp32)
__device__ __align__(16) __nv_bfloat16 g_hb1[NN * C1];  // bf16 copy of h1 for gather
__device__ __align__(16) __nv_bfloat16 g_hb2[NN * C2];  // bf16 copy of h2 for gather
__device__ __align__(16) float g_asrc1[NN * H1];
__device__ __align__(16) float g_adst1[NN * H1];
__device__ float g_asrc2[NN], g_adst2[NN];
__device__ float g_cnt[NG];
// CSR scratch
__device__ int g_hist[NN];
__device__ int g_indptr[NN + 1];
__device__ int g_off[NN];
__device__ int g_esrc[ET];

__device__ __forceinline__ float lrelu(float a) { return a > 0.f ? a : NEG_SLOPE * a; }
__device__ __forceinline__ float to_tf32(float x) {
    unsigned u;
    asm("cvt.rna.tf32.f32 %0, %1;" : "=r"(u) : "f"(x));
    return __uint_as_float(u);
}

// bf16x2 accumulate macros: constant indices only, no address-of-register
#define ACC4(RV, EV) do {                                                            \
    float2 _f0 = __bfloat1622float2(*reinterpret_cast<const __nv_bfloat162*>(&(RV).x)); \
    float2 _f1 = __bfloat1622float2(*reinterpret_cast<const __nv_bfloat162*>(&(RV).y)); \
    acc[0] += (EV) * _f0.x; acc[1] += (EV) * _f0.y;                                  \
    acc[2] += (EV) * _f1.x; acc[3] += (EV) * _f1.y;                                  \
} while (0)

#define ACC2(RV, EV) do {                                                            \
    float2 _f0 = __bfloat1622float2(*reinterpret_cast<const __nv_bfloat162*>(&(RV))); \
    acc[0] += (EV) * _f0.x; acc[1] += (EV) * _f0.y;                                  \
} while (0)

// ---------------- init: zero histogram + pool + cnt ----------------
__global__ void init_kernel(float* __restrict__ pool) {
    int i = blockIdx.x * blockDim.x + threadIdx.x;
    if (i < NN)      g_hist[i] = 0;
    if (i < NG * C2) pool[i] = 0.f;
    if (i < NG)      g_cnt[i] = 0.f;
}

// ---------------- CSR build: histogram of dst ----------------
__global__ void hist_kernel(const int* __restrict__ ei) {
    int e = blockIdx.x * blockDim.x + threadIdx.x;
    if (e >= ET) return;
    int dn = (e < NE) ? ei[NE + e] : (e - NE);
    atomicAdd(&g_hist[dn], 1);
}

// ---------------- CSR build: exclusive scan, thread-serial chunks + warp-shuffle block scan ----------------
__global__ void scan_kernel() {   // launch with 1024 threads, 1 block
    __shared__ int warp_sums[32];
    const int t = threadIdx.x;
    const int PER = (NN + 1023) / 1024;   // 49
    const int base = t * PER;

    int sum = 0;
    for (int j = 0; j < PER; j++) {
        int idx = base + j;
        if (idx < NN) sum += g_hist[idx];
    }
    const int lane = t & 31, wid = t >> 5;
    int v = sum;
#pragma unroll
    for (int d = 1; d < 32; d <<= 1) {
        int x = __shfl_up_sync(0xffffffffu, v, d);
        if (lane >= d) v += x;
    }
    if (lane == 31) warp_sums[wid] = v;
    __syncthreads();
    if (wid == 0) {
        int w = warp_sums[lane];
#pragma unroll
        for (int d = 1; d < 32; d <<= 1) {
            int x = __shfl_up_sync(0xffffffffu, w, d);
            if (lane >= d) w += x;
        }
        warp_sums[lane] = w;
    }
    __syncthreads();
    int running = (v - sum) + (wid > 0 ? warp_sums[wid - 1] : 0);
    for (int j = 0; j < PER; j++) {
        int idx = base + j;
        if (idx < NN) {
            g_indptr[idx] = running;
            g_off[idx]    = running;
            running += g_hist[idx];
        }
    }
    if (t == 1023) g_indptr[NN] = running;
}

// ---------------- CSR build: scatter src ids grouped by dst ----------------
__global__ void scatter_kernel(const int* __restrict__ ei) {
    int e = blockIdx.x * blockDim.x + threadIdx.x;
    if (e >= ET) return;
    int s, dn;
    if (e < NE) { s = ei[e]; dn = ei[NE + e]; }
    else        { s = dn = e - NE; }
    int pos = atomicAdd(&g_off[dn], 1);
    g_esrc[pos] = s;
}

// ---------------- TF32 tensor-core GEMM: C[M,N] = A[M,K] @ B[K,N], row-major fp32 ----------------
// Also writes bf16 copy Cb straight from registers.
// A smem [m][k] stride 20; B smem [k][n] stride 136 (no transpose, conflict-free).
__global__ __launch_bounds__(256) void gemm_tf32_kernel(
    const float* __restrict__ A, const float* __restrict__ B,
    float* __restrict__ C, __nv_bfloat16* __restrict__ Cb,
    int M, int N, int K)
{
    __shared__ __align__(16) float As[2][128][20];   // [buf][m][k]
    __shared__ __align__(16) float Bs[2][16][136];   // [buf][k][n]

    const int t    = threadIdx.x;
    const int lane = t & 31;
    const int wid  = t >> 5;
    const int g    = lane >> 2;
    const int tig  = lane & 3;
    const int wm   = (wid >> 2) * 64;
    const int wn   = (wid & 3) * 32;
    const int bm   = blockIdx.y * 128;
    const int bn   = blockIdx.x * 128;

    const int ar = t >> 2;
    const int ac = (t & 3) * 4;
    const int bkr = t >> 4;
    const int bnc = (t & 15) * 8;

    float acc[4][4][4];
#pragma unroll
    for (int i = 0; i < 4; i++)
#pragma unroll
        for (int j = 0; j < 4; j++)
#pragma unroll
            for (int r = 0; r < 4; r++) acc[i][j][r] = 0.f;

    const int NT = K / 16;
    float4 pa0, pa1, pb0, pb1;

    {
        pa0 = make_float4(0.f, 0.f, 0.f, 0.f); pa1 = pa0;
        if (bm + ar < M)      pa0 = *(const float4*)(A + (size_t)(bm + ar) * K + ac);
        if (bm + ar + 64 < M) pa1 = *(const float4*)(A + (size_t)(bm + ar + 64) * K + ac);
        pb0 = *(const float4*)(B + (size_t)bkr * N + bn + bnc);
        pb1 = *(const float4*)(B + (size_t)bkr * N + bn + bnc + 4);
        *(float4*)&As[0][ar][ac]      = make_float4(to_tf32(pa0.x), to_tf32(pa0.y), to_tf32(pa0.z), to_tf32(pa0.w));
        *(float4*)&As[0][ar + 64][ac] = make_float4(to_tf32(pa1.x), to_tf32(pa1.y), to_tf32(pa1.z), to_tf32(pa1.w));
        *(float4*)&Bs[0][bkr][bnc]     = make_float4(to_tf32(pb0.x), to_tf32(pb0.y), to_tf32(pb0.z), to_tf32(pb0.w));
        *(float4*)&Bs[0][bkr][bnc + 4] = make_float4(to_tf32(pb1.x), to_tf32(pb1.y), to_tf32(pb1.z), to_tf32(pb1.w));
    }
    __syncthreads();

    int buf = 0;
    for (int it = 0; it < NT; it++) {
        if (it + 1 < NT) {
            int k0 = (it + 1) * 16;
            pa0 = make_float4(0.f, 0.f, 0.f, 0.f); pa1 = pa0;
            if (bm + ar < M)      pa0 = *(const float4*)(A + (size_t)(bm + ar) * K + k0 + ac);
            if (bm + ar + 64 < M) pa1 = *(const float4*)(A + (size_t)(bm + ar + 64) * K + k0 + ac);
            pb0 = *(const float4*)(B + (size_t)(k0 + bkr) * N + bn + bnc);
            pb1 = *(const float4*)(B + (size_t)(k0 + bkr) * N + bn + bnc + 4);
        }
#pragma unroll
        for (int ks = 0; ks < 2; ks++) {
            const int kk = ks * 8;
            unsigned af[4][4], bf[4][2];
#pragma unroll
            for (int i = 0; i < 4; i++) {
                int r = wm + i * 16 + g;
                af[i][0] = __float_as_uint(As[buf][r][kk + tig]);
                af[i][1] = __float_as_uint(As[buf][r + 8][kk + tig]);
                af[i][2] = __float_as_uint(As[buf][r][kk + tig + 4]);
                af[i][3] = __float_as_uint(As[buf][r + 8][kk + tig + 4]);
            }
#pragma unroll
            for (int j = 0; j < 4; j++) {
                int n = wn + j * 8 + g;
                bf[j][0] = __float_as_uint(Bs[buf][kk + tig][n]);
                bf[j][1] = __float_as_uint(Bs[buf][kk + tig + 4][n]);
            }
#pragma unroll
            for (int i = 0; i < 4; i++)
#pragma unroll
                for (int j = 0; j < 4; j++) {
                    asm volatile(
                        "mma.sync.aligned.m16n8k8.row.col.f32.tf32.tf32.f32 "
                        "{%0,%1,%2,%3}, {%4,%5,%6,%7}, {%8,%9}, {%0,%1,%2,%3};"
                        : "+f"(acc[i][j][0]), "+f"(acc[i][j][1]),
                          "+f"(acc[i][j][2]), "+f"(acc[i][j][3])
                        : "r"(af[i][0]), "r"(af[i][1]), "r"(af[i][2]), "r"(af[i][3]),
                          "r"(bf[j][0]), "r"(bf[j][1]));
                }
        }
        if (it + 1 < NT) {
            int nb = buf ^ 1;
            *(float4*)&As[nb][ar][ac]      = make_float4(to_tf32(pa0.x), to_tf32(pa0.y), to_tf32(pa0.z), to_tf32(pa0.w));
            *(float4*)&As[nb][ar + 64][ac] = make_float4(to_tf32(pa1.x), to_tf32(pa1.y), to_tf32(pa1.z), to_tf32(pa1.w));
            *(float4*)&Bs[nb][bkr][bnc]     = make_float4(to_tf32(pb0.x), to_tf32(pb0.y), to_tf32(pb0.z), to_tf32(pb0.w));
            *(float4*)&Bs[nb][bkr][bnc + 4] = make_float4(to_tf32(pb1.x), to_tf32(pb1.y), to_tf32(pb1.z), to_tf32(pb1.w));
        }
        __syncthreads();
        buf ^= 1;
    }

#pragma unroll
    for (int i = 0; i < 4; i++) {
#pragma unroll
        for (int j = 0; j < 4; j++) {
            int row = bm + wm + i * 16 + g;
            int col = bn + wn + j * 8 + 2 * tig;
            if (row < M) {
                *(float2*)(C + (size_t)row * N + col) = make_float2(acc[i][j][0], acc[i][j][1]);
                __nv_bfloat162 bb = __floats2bfloat162_rn(acc[i][j][0], acc[i][j][1]);
                *(unsigned*)(Cb + (size_t)row * N + col) = *reinterpret_cast<unsigned*>(&bb);
            }
            if (row + 8 < M) {
                *(float2*)(C + (size_t)(row + 8) * N + col) = make_float2(acc[i][j][2], acc[i][j][3]);
                __nv_bfloat162 bb = __floats2bfloat162_rn(acc[i][j][2], acc[i][j][3]);
                *(unsigned*)(Cb + (size_t)(row + 8) * N + col) = *reinterpret_cast<unsigned*>(&bb);
            }
        }
    }
}

// ---------------- attention scores ----------------
__global__ void attn_scores_kernel(const float* __restrict__ h,
                                   const float* __restrict__ att_s,
                                   const float* __restrict__ att_d,
                                   float* __restrict__ asrc, float* __restrict__ adst,
                                   int heads, int ch)
{
    int i = blockIdx.x * blockDim.x + threadIdx.x;
    if (i >= NN * heads) return;
    int node = i / heads, hd = i - node * heads;
    const float4* hp = (const float4*)(h + (size_t)node * heads * ch + hd * ch);
    const float4* sp = (const float4*)(att_s + hd * ch);
    const float4* dp = (const float4*)(att_d + hd * ch);
    float s = 0.f, d = 0.f;
    for (int c = 0; c < ch / 4; c++) {
        float4 v = hp[c], a = sp[c], b = dp[c];
        s += v.x * a.x + v.y * a.y + v.z * a.z + v.w * a.w;
        d += v.x * b.x + v.y * b.y + v.z * b.z + v.w * b.w;
    }
    asrc[i] = s; adst[i] = d;
}

// ---------------- CSR aggregation: SPLIT warps per dst node (channel-split) ----------------
// Each warp owns C/SPLIT channels of one node; serial edge-loop length unchanged but
// per-warp bytes and burst depth halved; 2x finer work granularity for balance.
template <int H, int C, int SPLIT, bool POOL>
__global__ __launch_bounds__(256) void agg_kernel(
    const __nv_bfloat16* __restrict__ hb,
    const float* __restrict__ asrc, const float* __restrict__ adst,
    const float* __restrict__ bias,
    const int* __restrict__ batch,
    float* __restrict__ outp)
{
    int w = (blockIdx.x * blockDim.x + threadIdx.x) >> 5;
    int lane = threadIdx.x & 31;
    int n   = w / SPLIT;
    int sub = w % SPLIT;
    if (n >= NN) return;

    constexpr int CPL = C / (32 * SPLIT);     // 4 (layer1) or 2 (layer2)
    const int laneoff = sub * (C / SPLIT) + lane * CPL;
    const int hd = laneoff / (C / H);

    const float adn = adst[n * H + hd];
    const int beg = g_indptr[n];
    const int end = g_indptr[n + 1];

    float acc[CPL];
#pragma unroll
    for (int j = 0; j < CPL; j++) acc[j] = 0.f;
    float den = 0.f;

    int i = beg;

    if (CPL == 4) {
        for (; i + 3 < end; i += 4) {
            int s0 = g_esrc[i], s1 = g_esrc[i + 1], s2 = g_esrc[i + 2], s3 = g_esrc[i + 3];
            float a0 = asrc[s0 * H + hd], a1 = asrc[s1 * H + hd];
            float a2 = asrc[s2 * H + hd], a3 = asrc[s3 * H + hd];
            uint2 r0 = *(const uint2*)(hb + (size_t)s0 * C + laneoff);
            uint2 r1 = *(const uint2*)(hb + (size_t)s1 * C + laneoff);
            uint2 r2 = *(const uint2*)(hb + (size_t)s2 * C + laneoff);
            uint2 r3 = *(const uint2*)(hb + (size_t)s3 * C + laneoff);
            float e0 = __expf(lrelu(a0 + adn)), e1 = __expf(lrelu(a1 + adn));
            float e2 = __expf(lrelu(a2 + adn)), e3 = __expf(lrelu(a3 + adn));
            den += (e0 + e1) + (e2 + e3);
            ACC4(r0, e0); ACC4(r1, e1); ACC4(r2, e2); ACC4(r3, e3);
        }
        for (; i < end; i++) {
            int s = g_esrc[i];
            float a = asrc[s * H + hd];
            uint2 r = *(const uint2*)(hb + (size_t)s * C + laneoff);
            float e = __expf(lrelu(a + adn));
            den += e;
            ACC4(r, e);
        }
    } else {
        for (; i + 3 < end; i += 4) {
            int s0 = g_esrc[i], s1 = g_esrc[i + 1], s2 = g_esrc[i + 2], s3 = g_esrc[i + 3];
            float a0 = asrc[s0 * H + hd], a1 = asrc[s1 * H + hd];
            float a2 = asrc[s2 * H + hd], a3 = asrc[s3 * H + hd];
            unsigned r0 = *(const unsigned*)(hb + (size_t)s0 * C + laneoff);
            unsigned r1 = *(const unsigned*)(hb + (size_t)s1 * C + laneoff);
            unsigned r2 = *(const unsigned*)(hb + (size_t)s2 * C + laneoff);
            unsigned r3 = *(const unsigned*)(hb + (size_t)s3 * C + laneoff);
            float e0 = __expf(lrelu(a0 + adn)), e1 = __expf(lrelu(a1 + adn));
            float e2 = __expf(lrelu(a2 + adn)), e3 = __expf(lrelu(a3 + adn));
            den += (e0 + e1) + (e2 + e3);
            ACC2(r0, e0); ACC2(r1, e1); ACC2(r2, e2); ACC2(r3, e3);
        }
        for (; i < end; i++) {
            int s = g_esrc[i];
            float a = asrc[s * H + hd];
            unsigned r = *(const unsigned*)(hb + (size_t)s * C + laneoff);
            float e = __expf(lrelu(a + adn));
            den += e;
            ACC2(r, e);
        }
    }

    const float inv = 1.f / (den + EPSV);
    if (POOL) {
        int g = batch[n];
        float* pp = outp + (size_t)g * C + laneoff;
#pragma unroll
        for (int j = 0; j < CPL; j++) {
            float v = acc[j] * inv + bias[laneoff + j];
            v = v > 0.f ? v : 0.f;
            atomicAdd(pp + j, v);
        }
    } else {
        float* op = outp + (size_t)n * C + laneoff;
#pragma unroll
        for (int j = 0; j < CPL; j++) {
            float v = acc[j] * inv + bias[laneoff + j];
            acc[j] = v > 0.f ? v : 0.f;
        }
        if (CPL == 4) {
            *(float4*)op = make_float4(acc[0], acc[1], acc[2], acc[3]);
        } else {
            *(float2*)op = make_float2(acc[0], acc[1]);
        }
    }
}

// ---------------- node count per graph ----------------
__global__ void cnt_kernel(const int* __restrict__ batch) {
    int n = blockIdx.x * blockDim.x + threadIdx.x;
    if (n >= NN) return;
    atomicAdd(&g_cnt[batch[n]], 1.0f);
}

__global__ void pool_div_kernel(float* __restrict__ pool) {
    int i = blockIdx.x * blockDim.x + threadIdx.x;
    if (i >= NG * C2) return;
    int g = i >> 7;
    float c = g_cnt[g];
    pool[i] = pool[i] / (c > 1.f ? c : 1.f);
}

// ---------------- host launcher (graph-capturable, default stream) ----------------
extern "C" void kernel_launch(void* const* d_in, const int* in_sizes, int n_in,
                              void* d_out, int out_size)
{
    const float* x    = (const float*)d_in[0];
    const float* W1   = (const float*)d_in[1];
    const float* as1  = (const float*)d_in[2];
    const float* ad1  = (const float*)d_in[3];
    const float* b1   = (const float*)d_in[4];
    const float* W2   = (const float*)d_in[5];
    const float* as2  = (const float*)d_in[6];
    const float* ad2  = (const float*)d_in[7];
    const float* b2   = (const float*)d_in[8];
    const int*   ei   = (const int*)d_in[9];
    const int*   batch= (const int*)d_in[10];
    float* pool = (float*)d_out;

    float *p_h1, *p_out1, *p_h2;
    float *p_asrc1, *p_adst1, *p_asrc2, *p_adst2;
    __nv_bfloat16 *p_hb1, *p_hb2;
    cudaGetSymbolAddress((void**)&p_h1, g_h1);
    cudaGetSymbolAddress((void**)&p_out1, g_out1);
    cudaGetSymbolAddress((void**)&p_h2, g_h2);
    cudaGetSymbolAddress((void**)&p_hb1, g_hb1);
    cudaGetSymbolAddress((void**)&p_hb2, g_hb2);
    cudaGetSymbolAddress((void**)&p_asrc1, g_asrc1);
    cudaGetSymbolAddress((void**)&p_adst1, g_adst1);
    cudaGetSymbolAddress((void**)&p_asrc2, g_asrc2);
    cudaGetSymbolAddress((void**)&p_adst2, g_adst2);

    const int TB = 256;

    // 1) init (hist/pool/cnt)
    init_kernel<<<(NN + TB - 1) / TB, TB>>>(pool);
    // 2) histogram
    hist_kernel<<<(ET + TB - 1) / TB, TB>>>(ei);
    // 3) scan
    scan_kernel<<<1, 1024>>>();
    // 4) gemm1 (profiler slot 4)
    {
        dim3 grid(C1 / 128, (NN + 127) / 128);
        gemm_tf32_kernel<<<grid, 256>>>(x, W1, p_h1, p_hb1, NN, C1, 256);
    }
    // 5) scatter (completes CSR)
    scatter_kernel<<<(ET + TB - 1) / TB, TB>>>(ei);
    // 6) attention scores layer 1
    attn_scores_kernel<<<(NN * H1 + TB - 1) / TB, TB>>>(p_h1, as1, ad1, p_asrc1, p_adst1, H1, CH1);
    // 7) CSR aggregation layer 1 (2 warps/node) -> g_out1
    agg_kernel<H1, C1, 2, false><<<((long long)NN * 2 * 32 + TB - 1) / TB, TB>>>(
        p_hb1, p_asrc1, p_adst1, b1, batch, p_out1);
    // 8) gemm2
    {
        dim3 grid(C2 / 128, (NN + 127) / 128);
        gemm_tf32_kernel<<<grid, 256>>>(p_out1, W2, p_h2, p_hb2, NN, C2, 256);
    }
    // 9) attention scores layer 2
    attn_scores_kernel<<<(NN + TB - 1) / TB, TB>>>(p_h2, as2, ad2, p_asrc2, p_adst2, 1, C2);
    // 10) graph node counts
    cnt_kernel<<<(NN + TB - 1) / TB, TB>>>(batch);
    // 11) CSR aggregation layer 2 (2 warps/node) -> pool
    agg_kernel<1, C2, 2, true><<<((long long)NN * 2 * 32 + TB - 1) / TB, TB>>>(
        p_hb2, p_asrc2, p_adst2, b2, batch, pool);
    // 12) mean
    pool_div_kernel<<<(NG * C2 + TB - 1) / TB, TB>>>(pool);
}